// round 4
// baseline (speedup 1.0000x reference)
#include <cuda_runtime.h>
#include <cstdio>

#define Nn   50000
#define Ee   800000
#define INF_ 500
#define HIDF 128
#define KK   10     // K (polynomial order); K+1 = 11 coefficients

// ------------------------- device scratch (static, no allocs) ---------------
__device__ int   g_deg[Nn];
__device__ int   g_cur[Nn];
__device__ int   g_off[Nn + 1];
__device__ float g_dinv[Nn];
__device__ int2  g_sw[Ee];                         // packed {src, __float_as_int(w)}
__device__ int   g_bsum[256];
__device__ int   g_boff[256];
__device__ float g_P[KK + 1][(size_t)Nn * HIDF];   // Krylov basis p_j = A^j h  (~282 MB)
__device__ float g_accL[(size_t)Nn * HIDF];
__device__ float g_accH[(size_t)Nn * HIDF];
__device__ float g_sum[4 * HIDF];                  // sumL, sqL, sumH, sqH
__device__ float g_cL[KK + 1];
__device__ float g_cH[KK + 1];
__device__ float g_alpha[2 * HIDF];                // per-branch BN scale  (L then H)
__device__ float g_beta[2 * HIDF];                 // per-branch BN shift

// ------------------------- f32x2 packed-FMA helpers --------------------------
__device__ __forceinline__ unsigned long long pack2(float lo, float hi) {
    unsigned long long r;
    asm("mov.b64 %0, {%1, %2};" : "=l"(r) : "f"(lo), "f"(hi));
    return r;
}
__device__ __forceinline__ void unpack2(unsigned long long p, float& lo, float& hi) {
    asm("mov.b64 {%0, %1}, %2;" : "=f"(lo), "=f"(hi) : "l"(p));
}
#define FMA2(d, a, b, c) \
    asm("fma.rn.f32x2 %0, %1, %2, %3;" : "=l"(d) : "l"(a), "l"(b), "l"(c))

// ------------------------------- small kernels -------------------------------
__global__ void k_init() {
    int i = blockIdx.x * blockDim.x + threadIdx.x;
    if (i < Nn) { g_deg[i] = 0; g_cur[i] = 0; }
    if (i < 4 * HIDF) g_sum[i] = 0.f;
    if (i == 0) g_off[Nn] = Ee;
}

__global__ void k_deg(const int* __restrict__ dst) {
    int e = blockIdx.x * blockDim.x + threadIdx.x;
    if (e < Ee) atomicAdd(&g_deg[dst[e]], 1);
}

// block sums for the scan + dinv in the same pass
__global__ void k_blocksum() {
    int i = blockIdx.x * 256 + threadIdx.x;
    int v = (i < Nn) ? g_deg[i] : 0;
    if (i < Nn) g_dinv[i] = rsqrtf(fmaxf((float)v, 1.f));
    int s = v;
#pragma unroll
    for (int o = 16; o; o >>= 1) s += __shfl_down_sync(~0u, s, o);
    __shared__ int ws[8];
    if ((threadIdx.x & 31) == 0) ws[threadIdx.x >> 5] = s;
    __syncthreads();
    if (threadIdx.x < 8) {
        int t = ws[threadIdx.x];
#pragma unroll
        for (int o = 4; o; o >>= 1) t += __shfl_down_sync(0xff, t, o);
        if (threadIdx.x == 0) g_bsum[blockIdx.x] = t;
    }
}

__global__ void k_scanb(int nb) {   // single block; exclusive scan of block sums
    int t = threadIdx.x;
    int lane = t & 31, wid = t >> 5;
    int v = (t < nb) ? g_bsum[t] : 0;
    int s = v;
#pragma unroll
    for (int o = 1; o < 32; o <<= 1) {
        int u = __shfl_up_sync(~0u, s, o);
        if (lane >= o) s += u;
    }
    __shared__ int ws[8];
    if (lane == 31) ws[wid] = s;
    __syncthreads();
    if (t < 8) {
        int u = ws[t];
#pragma unroll
        for (int o = 1; o < 8; o <<= 1) {
            int q = __shfl_up_sync(0xff, u, o);
            if (t >= o) u += q;
        }
        ws[t] = u;
    }
    __syncthreads();
    int excl = s - v + (wid ? ws[wid - 1] : 0);
    if (t < nb) g_boff[t] = excl;
}

__global__ void k_scanwrite() {
    int i = blockIdx.x * 256 + threadIdx.x;
    int lane = threadIdx.x & 31, wid = threadIdx.x >> 5;
    int v = (i < Nn) ? g_deg[i] : 0;
    int s = v;
#pragma unroll
    for (int o = 1; o < 32; o <<= 1) {
        int u = __shfl_up_sync(~0u, s, o);
        if (lane >= o) s += u;
    }
    __shared__ int ws[8];
    if (lane == 31) ws[wid] = s;
    __syncthreads();
    if (threadIdx.x < 8) {
        int u = ws[threadIdx.x];
#pragma unroll
        for (int o = 1; o < 8; o <<= 1) {
            int q = __shfl_up_sync(0xff, u, o);
            if (threadIdx.x >= o) u += q;
        }
        ws[threadIdx.x] = u;
    }
    __syncthreads();
    int excl = s - v + (wid ? ws[wid - 1] : 0);
    if (i < Nn) g_off[i] = g_boff[blockIdx.x] + excl;
}

__global__ void k_scatter(const int* __restrict__ src, const int* __restrict__ dst) {
    int e = blockIdx.x * blockDim.x + threadIdx.x;
    if (e < Ee) {
        int s = src[e], d = dst[e];
        int p = atomicAdd(&g_cur[d], 1);
        int idx = g_off[d] + p;
        float w = g_dinv[s] * g_dinv[d];
        g_sw[idx] = make_int2(s, __float_as_int(w));
    }
}

// c_L[j] = gamma_L[j];  c_H[j] = (-1)^j * sum_{k>=j} gamma_H[k] * C(k,j)
__global__ void k_coeff(const float* __restrict__ gL, const float* __restrict__ gH) {
    if (threadIdx.x == 0 && blockIdx.x == 0) {
        double C[KK + 1][KK + 1];
        for (int k = 0; k <= KK; k++)
            for (int j = 0; j <= KK; j++) C[k][j] = 0.0;
        for (int k = 0; k <= KK; k++) {
            C[k][0] = 1.0; C[k][k] = 1.0;
            for (int j = 1; j < k; j++) C[k][j] = C[k - 1][j - 1] + C[k - 1][j];
        }
        for (int j = 0; j <= KK; j++) {
            double s = 0.0;
            for (int k = j; k <= KK; k++) s += (double)gH[k] * C[k][j];
            g_cH[j] = (j & 1) ? (float)(-s) : (float)s;
            g_cL[j] = gL[j];
        }
    }
}

// --------------------------- tiled fp32 GEMM (f32x2 inner) -------------------
// C[M,128] = op(A[M,KDIM]) @ B[KDIM,128] (+bias)(+relu). BM=128, BN=128,
// BK=16, 256 threads, 8x8 micro-tile, packed fma.rn.f32x2.
// AFFINE: A element -> A*alpha[col]+beta[col] (per-branch pointers passed in).
template <int KDIM, bool AFFINE, bool RELU>
__global__ __launch_bounds__(256)
void k_gemm(const float* __restrict__ A, const float* __restrict__ B,
            const float* __restrict__ bias,
            const float* __restrict__ alpha, const float* __restrict__ beta,
            float* __restrict__ C, int M) {
    __shared__ __align__(16) float As[128][17];
    __shared__ __align__(16) float Bs[16][132];
    int tid = threadIdx.x;
    int tx = tid & 15, ty = tid >> 4;
    int row0 = blockIdx.x * 128;
    unsigned long long acc2[8][4];
#pragma unroll
    for (int i = 0; i < 8; i++)
#pragma unroll
        for (int j = 0; j < 4; j++) acc2[i][j] = 0ull;

    for (int k0 = 0; k0 < KDIM; k0 += 16) {
#pragma unroll
        for (int i = tid; i < 128 * 16; i += 256) {
            int r = i >> 4, c = i & 15;
            int gr = row0 + r, gc = k0 + c;
            float v = 0.f;
            if (gr < M && gc < KDIM) {
                v = A[(size_t)gr * KDIM + gc];
                if (AFFINE) v = fmaf(v, alpha[gc], beta[gc]);
            }
            As[r][c] = v;
        }
#pragma unroll
        for (int i = tid; i < 16 * 128; i += 256) {
            int r = i >> 7, c = i & 127;
            int gk = k0 + r;
            Bs[r][c] = (gk < KDIM) ? B[(size_t)gk * 128 + c] : 0.f;
        }
        __syncthreads();
#pragma unroll
        for (int k = 0; k < 16; k++) {
            const ulonglong2* brow = (const ulonglong2*)&Bs[k][tx * 8];
            ulonglong2 q0 = brow[0];   // cols 0-3
            ulonglong2 q1 = brow[1];   // cols 4-7
#pragma unroll
            for (int i = 0; i < 8; i++) {
                float a = As[ty * 8 + i][k];
                unsigned long long aa = pack2(a, a);
                FMA2(acc2[i][0], aa, q0.x, acc2[i][0]);
                FMA2(acc2[i][1], aa, q0.y, acc2[i][1]);
                FMA2(acc2[i][2], aa, q1.x, acc2[i][2]);
                FMA2(acc2[i][3], aa, q1.y, acc2[i][3]);
            }
        }
        __syncthreads();
    }
#pragma unroll
    for (int i = 0; i < 8; i++) {
        int gr = row0 + ty * 8 + i;
        if (gr < M) {
#pragma unroll
            for (int j = 0; j < 4; j++) {
                float lo, hi;
                unpack2(acc2[i][j], lo, hi);
                int gc = tx * 8 + 2 * j;
                lo += bias[gc]; hi += bias[gc + 1];
                if (RELU) { lo = fmaxf(lo, 0.f); hi = fmaxf(hi, 0.f); }
                C[(size_t)gr * 128 + gc]     = lo;
                C[(size_t)gr * 128 + gc + 1] = hi;
            }
        }
    }
}

// Epilogue wrapper: both branches in one launch (blockIdx.y = branch).
__global__ __launch_bounds__(256)
void k_gemm_ep(const float* __restrict__ AL, const float* __restrict__ AH,
               const float* __restrict__ B, const float* __restrict__ bias,
               float* __restrict__ out, int M);

// --------------------------- sparse propagation ------------------------------
// one warp per dst node; each lane owns 4 features (16B). Edge metadata for
// up to 32 edges is fetched by a single coalesced lane-parallel LDG.64 and
// broadcast via shfl; gathers are issued 8-deep for MLP.
__global__ __launch_bounds__(256)
void k_prop(int j) {
    int node = blockIdx.x * 8 + (threadIdx.x >> 5);
    if (node >= Nn) return;
    int lane = threadIdx.x & 31;
    const ulonglong2* __restrict__ tin = (const ulonglong2*)g_P[j - 1];
    ulonglong2* __restrict__ tout = (ulonglong2*)g_P[j];
    int beg = g_off[node], end = g_off[node + 1];
    unsigned long long accA = 0ull, accB = 0ull;   // 4 features as 2 f32x2

    for (int base = beg; base < end; base += 32) {
        int cnt = min(32, end - base);
        int2 my = make_int2(0, 0);
        if (lane < cnt) my = g_sw[base + lane];
        int i = 0;
        for (; i + 8 <= cnt; i += 8) {
            int s0 = __shfl_sync(~0u, my.x, i + 0);
            int s1 = __shfl_sync(~0u, my.x, i + 1);
            int s2 = __shfl_sync(~0u, my.x, i + 2);
            int s3 = __shfl_sync(~0u, my.x, i + 3);
            int s4 = __shfl_sync(~0u, my.x, i + 4);
            int s5 = __shfl_sync(~0u, my.x, i + 5);
            int s6 = __shfl_sync(~0u, my.x, i + 6);
            int s7 = __shfl_sync(~0u, my.x, i + 7);
            ulonglong2 v0 = tin[s0 * 32 + lane];
            ulonglong2 v1 = tin[s1 * 32 + lane];
            ulonglong2 v2 = tin[s2 * 32 + lane];
            ulonglong2 v3 = tin[s3 * 32 + lane];
            ulonglong2 v4 = tin[s4 * 32 + lane];
            ulonglong2 v5 = tin[s5 * 32 + lane];
            ulonglong2 v6 = tin[s6 * 32 + lane];
            ulonglong2 v7 = tin[s7 * 32 + lane];
            float w0 = __int_as_float(__shfl_sync(~0u, my.y, i + 0));
            float w1 = __int_as_float(__shfl_sync(~0u, my.y, i + 1));
            float w2 = __int_as_float(__shfl_sync(~0u, my.y, i + 2));
            float w3 = __int_as_float(__shfl_sync(~0u, my.y, i + 3));
            float w4 = __int_as_float(__shfl_sync(~0u, my.y, i + 4));
            float w5 = __int_as_float(__shfl_sync(~0u, my.y, i + 5));
            float w6 = __int_as_float(__shfl_sync(~0u, my.y, i + 6));
            float w7 = __int_as_float(__shfl_sync(~0u, my.y, i + 7));
            unsigned long long p;
            p = pack2(w0, w0); FMA2(accA, p, v0.x, accA); FMA2(accB, p, v0.y, accB);
            p = pack2(w1, w1); FMA2(accA, p, v1.x, accA); FMA2(accB, p, v1.y, accB);
            p = pack2(w2, w2); FMA2(accA, p, v2.x, accA); FMA2(accB, p, v2.y, accB);
            p = pack2(w3, w3); FMA2(accA, p, v3.x, accA); FMA2(accB, p, v3.y, accB);
            p = pack2(w4, w4); FMA2(accA, p, v4.x, accA); FMA2(accB, p, v4.y, accB);
            p = pack2(w5, w5); FMA2(accA, p, v5.x, accA); FMA2(accB, p, v5.y, accB);
            p = pack2(w6, w6); FMA2(accA, p, v6.x, accA); FMA2(accB, p, v6.y, accB);
            p = pack2(w7, w7); FMA2(accA, p, v7.x, accA); FMA2(accB, p, v7.y, accB);
        }
        for (; i < cnt; i++) {
            int s0 = __shfl_sync(~0u, my.x, i);
            float w0 = __int_as_float(__shfl_sync(~0u, my.y, i));
            ulonglong2 v0 = tin[s0 * 32 + lane];
            unsigned long long p = pack2(w0, w0);
            FMA2(accA, p, v0.x, accA);
            FMA2(accB, p, v0.y, accB);
        }
    }
    ulonglong2 o; o.x = accA; o.y = accB;
    tout[node * 32 + lane] = o;
}

// --------------------------- combine + BN partials ---------------------------
__global__ __launch_bounds__(256)
void k_combine() {
    int tid = threadIdx.x;
    int fq = tid & 31;         // feature quad: features 4*fq .. 4*fq+3
    int wid = tid >> 5;
    float cl[KK + 1], ch[KK + 1];
#pragma unroll
    for (int j = 0; j <= KK; j++) { cl[j] = g_cL[j]; ch[j] = g_cH[j]; }

    float4 psL = {0, 0, 0, 0}, pqL = {0, 0, 0, 0};
    float4 psH = {0, 0, 0, 0}, pqH = {0, 0, 0, 0};

    for (int node = blockIdx.x * 8 + wid; node < Nn; node += gridDim.x * 8) {
        int base = node * 32 + fq;
        float4 aL = {0, 0, 0, 0}, aH = {0, 0, 0, 0};
#pragma unroll
        for (int j = 0; j <= KK; j++) {
            float4 p = ((const float4*)g_P[j])[base];
            aL.x = fmaf(cl[j], p.x, aL.x); aL.y = fmaf(cl[j], p.y, aL.y);
            aL.z = fmaf(cl[j], p.z, aL.z); aL.w = fmaf(cl[j], p.w, aL.w);
            aH.x = fmaf(ch[j], p.x, aH.x); aH.y = fmaf(ch[j], p.y, aH.y);
            aH.z = fmaf(ch[j], p.z, aH.z); aH.w = fmaf(ch[j], p.w, aH.w);
        }
        ((float4*)g_accL)[base] = aL;
        ((float4*)g_accH)[base] = aH;
        psL.x += aL.x; psL.y += aL.y; psL.z += aL.z; psL.w += aL.w;
        pqL.x = fmaf(aL.x, aL.x, pqL.x); pqL.y = fmaf(aL.y, aL.y, pqL.y);
        pqL.z = fmaf(aL.z, aL.z, pqL.z); pqL.w = fmaf(aL.w, aL.w, pqL.w);
        psH.x += aH.x; psH.y += aH.y; psH.z += aH.z; psH.w += aH.w;
        pqH.x = fmaf(aH.x, aH.x, pqH.x); pqH.y = fmaf(aH.y, aH.y, pqH.y);
        pqH.z = fmaf(aH.z, aH.z, pqH.z); pqH.w = fmaf(aH.w, aH.w, pqH.w);
    }

    __shared__ float4 sh[4][256];
    sh[0][tid] = psL; sh[1][tid] = pqL; sh[2][tid] = psH; sh[3][tid] = pqH;
    __syncthreads();
    if (tid < 32) {
        float4 a0 = sh[0][tid], a1 = sh[1][tid], a2 = sh[2][tid], a3 = sh[3][tid];
#pragma unroll
        for (int w = 1; w < 8; w++) {
            float4 t;
            t = sh[0][tid + 32 * w]; a0.x += t.x; a0.y += t.y; a0.z += t.z; a0.w += t.w;
            t = sh[1][tid + 32 * w]; a1.x += t.x; a1.y += t.y; a1.z += t.z; a1.w += t.w;
            t = sh[2][tid + 32 * w]; a2.x += t.x; a2.y += t.y; a2.z += t.z; a2.w += t.w;
            t = sh[3][tid + 32 * w]; a3.x += t.x; a3.y += t.y; a3.z += t.z; a3.w += t.w;
        }
        int f = tid * 4;
        atomicAdd(&g_sum[0 * HIDF + f + 0], a0.x); atomicAdd(&g_sum[0 * HIDF + f + 1], a0.y);
        atomicAdd(&g_sum[0 * HIDF + f + 2], a0.z); atomicAdd(&g_sum[0 * HIDF + f + 3], a0.w);
        atomicAdd(&g_sum[1 * HIDF + f + 0], a1.x); atomicAdd(&g_sum[1 * HIDF + f + 1], a1.y);
        atomicAdd(&g_sum[1 * HIDF + f + 2], a1.z); atomicAdd(&g_sum[1 * HIDF + f + 3], a1.w);
        atomicAdd(&g_sum[2 * HIDF + f + 0], a2.x); atomicAdd(&g_sum[2 * HIDF + f + 1], a2.y);
        atomicAdd(&g_sum[2 * HIDF + f + 2], a2.z); atomicAdd(&g_sum[2 * HIDF + f + 3], a2.w);
        atomicAdd(&g_sum[3 * HIDF + f + 0], a3.x); atomicAdd(&g_sum[3 * HIDF + f + 1], a3.y);
        atomicAdd(&g_sum[3 * HIDF + f + 2], a3.z); atomicAdd(&g_sum[3 * HIDF + f + 3], a3.w);
    }
}

__global__ void k_bnfinal(const float* __restrict__ bn_scale,
                          const float* __restrict__ bn_shift) {
    int f = threadIdx.x;
    if (f < HIDF) {
        const float invN = 1.f / (float)Nn;
        float mu = g_sum[f] * invN;
        float var = g_sum[HIDF + f] * invN - mu * mu;
        float a = rsqrtf(var + 1e-5f) * bn_scale[f];
        g_alpha[f] = a;
        g_beta[f] = bn_shift[f] - mu * a;
        mu = g_sum[2 * HIDF + f] * invN;
        var = g_sum[3 * HIDF + f] * invN - mu * mu;
        a = rsqrtf(var + 1e-5f) * bn_scale[f];
        g_alpha[HIDF + f] = a;
        g_beta[HIDF + f] = bn_shift[f] - mu * a;
    }
}

// Epilogue: pick branch by blockIdx.y, then run the shared GEMM body via
// a device-side inline of the same algorithm (instantiated with AFFINE+RELU).
__global__ __launch_bounds__(256)
void k_gemm_ep(const float* __restrict__ AL, const float* __restrict__ AH,
               const float* __restrict__ B, const float* __restrict__ bias,
               float* __restrict__ out, int M) {
    __shared__ __align__(16) float As[128][17];
    __shared__ __align__(16) float Bs[16][132];
    int br = blockIdx.y;
    const float* __restrict__ A = br ? AH : AL;
    const float* __restrict__ alpha = g_alpha + br * HIDF;
    const float* __restrict__ beta  = g_beta  + br * HIDF;
    float* __restrict__ C = out + (size_t)br * Nn * HIDF;

    int tid = threadIdx.x;
    int tx = tid & 15, ty = tid >> 4;
    int row0 = blockIdx.x * 128;
    unsigned long long acc2[8][4];
#pragma unroll
    for (int i = 0; i < 8; i++)
#pragma unroll
        for (int j = 0; j < 4; j++) acc2[i][j] = 0ull;

    for (int k0 = 0; k0 < HIDF; k0 += 16) {
#pragma unroll
        for (int i = tid; i < 128 * 16; i += 256) {
            int r = i >> 4, c = i & 15;
            int gr = row0 + r, gc = k0 + c;
            float v = 0.f;
            if (gr < M) v = fmaf(A[(size_t)gr * HIDF + gc], alpha[gc], beta[gc]);
            As[r][c] = v;
        }
#pragma unroll
        for (int i = tid; i < 16 * 128; i += 256) {
            int r = i >> 7, c = i & 127;
            Bs[r][c] = B[(size_t)(k0 + r) * 128 + c];
        }
        __syncthreads();
#pragma unroll
        for (int k = 0; k < 16; k++) {
            const ulonglong2* brow = (const ulonglong2*)&Bs[k][tx * 8];
            ulonglong2 q0 = brow[0];
            ulonglong2 q1 = brow[1];
#pragma unroll
            for (int i = 0; i < 8; i++) {
                float a = As[ty * 8 + i][k];
                unsigned long long aa = pack2(a, a);
                FMA2(acc2[i][0], aa, q0.x, acc2[i][0]);
                FMA2(acc2[i][1], aa, q0.y, acc2[i][1]);
                FMA2(acc2[i][2], aa, q1.x, acc2[i][2]);
                FMA2(acc2[i][3], aa, q1.y, acc2[i][3]);
            }
        }
        __syncthreads();
    }
#pragma unroll
    for (int i = 0; i < 8; i++) {
        int gr = row0 + ty * 8 + i;
        if (gr < M) {
#pragma unroll
            for (int j = 0; j < 4; j++) {
                float lo, hi;
                unpack2(acc2[i][j], lo, hi);
                int gc = tx * 8 + 2 * j;
                C[(size_t)gr * 128 + gc]     = fmaxf(lo + bias[gc], 0.f);
                C[(size_t)gr * 128 + gc + 1] = fmaxf(hi + bias[gc + 1], 0.f);
            }
        }
    }
}

// ------------------------------- launcher ------------------------------------
extern "C" void kernel_launch(void* const* d_in, const int* in_sizes, int n_in,
                              void* d_out, int out_size) {
    const float* x    = (const float*)d_in[0];
    const int*   ei   = (const int*)d_in[1];
    const float* W_in = (const float*)d_in[2];
    const float* b_in = (const float*)d_in[3];
    const float* gL   = (const float*)d_in[4];
    const float* gH   = (const float*)d_in[5];
    const float* bns  = (const float*)d_in[6];
    const float* bnb  = (const float*)d_in[7];
    const float* W_up = (const float*)d_in[8];
    const float* b_up = (const float*)d_in[9];
    float* out = (float*)d_out;

    const int* src = ei;
    const int* dst = ei + Ee;

    void *pP, *pAL, *pAH;
    cudaGetSymbolAddress(&pP,  g_P);
    cudaGetSymbolAddress(&pAL, g_accL);
    cudaGetSymbolAddress(&pAH, g_accH);
    float* P0   = (float*)pP;                  // g_P[0]
    float* accL = (float*)pAL;
    float* accH = (float*)pAH;

    const int nblkN = (Nn + 255) / 256;   // 196
    const int nblkE = (Ee + 255) / 256;   // 3125
    const int gemmB = (Nn + 127) / 128;   // 391

    k_init<<<nblkN, 256>>>();
    k_deg<<<nblkE, 256>>>(dst);
    k_blocksum<<<nblkN, 256>>>();
    k_scanb<<<1, 256>>>(nblkN);
    k_scanwrite<<<nblkN, 256>>>();
    k_scatter<<<nblkE, 256>>>(src, dst);
    k_coeff<<<1, 32>>>(gL, gH);

    // p_0 = h = x @ W_in + b_in
    k_gemm<INF_, false, false><<<gemmB, 256>>>(x, W_in, b_in, nullptr, nullptr, P0, Nn);

    // Krylov chain p_j = A p_{j-1}
    for (int j = 1; j <= KK; j++)
        k_prop<<<(Nn + 7) / 8, 256>>>(j);

    // acc_L / acc_H + BN statistics
    k_combine<<<592, 256>>>();
    k_bnfinal<<<1, 128>>>(bns, bnb);

    // Z = relu(BN(acc) @ W_up + b_up), both branches in one launch
    dim3 epg(gemmB, 2);
    k_gemm_ep<<<epg, 256>>>(accL, accH, W_up, b_up, out, Nn);
}

// round 5
// speedup vs baseline: 1.0296x; 1.0296x over previous
#include <cuda_runtime.h>
#include <cstdio>

#define Nn   50000
#define Ee   800000
#define INF_ 500
#define HIDF 128
#define KK   10     // K (polynomial order); K+1 = 11 coefficients

// ------------------------- device scratch (static, no allocs) ---------------
__device__ int   g_deg[Nn];
__device__ int   g_cur[Nn];
__device__ int   g_off[Nn + 1];
__device__ float g_dinv[Nn];
__device__ int2  g_sw[Ee];                         // packed {src, __float_as_int(w)}
__device__ int   g_bsum[256];
__device__ int   g_boff[256];
__device__ float g_P[KK + 1][(size_t)Nn * HIDF];   // Krylov basis p_j = A^j h  (~282 MB)
__device__ float g_accL[(size_t)Nn * HIDF];
__device__ float g_accH[(size_t)Nn * HIDF];
__device__ float g_sum[4 * HIDF];                  // sumL, sqL, sumH, sqH
__device__ float g_cL[KK + 1];
__device__ float g_cH[KK + 1];
__device__ float g_alpha[2 * HIDF];                // per-branch BN scale  (L then H)
__device__ float g_beta[2 * HIDF];                 // per-branch BN shift

// ------------------------- f32x2 packed-FMA helpers --------------------------
__device__ __forceinline__ unsigned long long pack2(float lo, float hi) {
    unsigned long long r;
    asm("mov.b64 %0, {%1, %2};" : "=l"(r) : "f"(lo), "f"(hi));
    return r;
}
__device__ __forceinline__ void unpack2(unsigned long long p, float& lo, float& hi) {
    asm("mov.b64 {%0, %1}, %2;" : "=f"(lo), "=f"(hi) : "l"(p));
}
#define FMA2(d, a, b, c) \
    asm("fma.rn.f32x2 %0, %1, %2, %3;" : "=l"(d) : "l"(a), "l"(b), "l"(c))

// ------------------------------- small kernels -------------------------------
__global__ void k_init() {
    int i = blockIdx.x * blockDim.x + threadIdx.x;
    if (i < Nn) { g_deg[i] = 0; g_cur[i] = 0; }
    if (i < 4 * HIDF) g_sum[i] = 0.f;
    if (i == 0) g_off[Nn] = Ee;
}

__global__ void k_deg(const int* __restrict__ dst) {
    int e = blockIdx.x * blockDim.x + threadIdx.x;
    if (e < Ee) atomicAdd(&g_deg[dst[e]], 1);
}

// block sums for the scan + dinv in the same pass
__global__ void k_blocksum() {
    int i = blockIdx.x * 256 + threadIdx.x;
    int v = (i < Nn) ? g_deg[i] : 0;
    if (i < Nn) g_dinv[i] = rsqrtf(fmaxf((float)v, 1.f));
    int s = v;
#pragma unroll
    for (int o = 16; o; o >>= 1) s += __shfl_down_sync(~0u, s, o);
    __shared__ int ws[8];
    if ((threadIdx.x & 31) == 0) ws[threadIdx.x >> 5] = s;
    __syncthreads();
    if (threadIdx.x < 8) {
        int t = ws[threadIdx.x];
#pragma unroll
        for (int o = 4; o; o >>= 1) t += __shfl_down_sync(0xff, t, o);
        if (threadIdx.x == 0) g_bsum[blockIdx.x] = t;
    }
}

__global__ void k_scanb(int nb) {   // single block; exclusive scan of block sums
    int t = threadIdx.x;
    int lane = t & 31, wid = t >> 5;
    int v = (t < nb) ? g_bsum[t] : 0;
    int s = v;
#pragma unroll
    for (int o = 1; o < 32; o <<= 1) {
        int u = __shfl_up_sync(~0u, s, o);
        if (lane >= o) s += u;
    }
    __shared__ int ws[8];
    if (lane == 31) ws[wid] = s;
    __syncthreads();
    if (t < 8) {
        int u = ws[t];
#pragma unroll
        for (int o = 1; o < 8; o <<= 1) {
            int q = __shfl_up_sync(0xff, u, o);
            if (t >= o) u += q;
        }
        ws[t] = u;
    }
    __syncthreads();
    int excl = s - v + (wid ? ws[wid - 1] : 0);
    if (t < nb) g_boff[t] = excl;
}

__global__ void k_scanwrite() {
    int i = blockIdx.x * 256 + threadIdx.x;
    int lane = threadIdx.x & 31, wid = threadIdx.x >> 5;
    int v = (i < Nn) ? g_deg[i] : 0;
    int s = v;
#pragma unroll
    for (int o = 1; o < 32; o <<= 1) {
        int u = __shfl_up_sync(~0u, s, o);
        if (lane >= o) s += u;
    }
    __shared__ int ws[8];
    if (lane == 31) ws[wid] = s;
    __syncthreads();
    if (threadIdx.x < 8) {
        int u = ws[threadIdx.x];
#pragma unroll
        for (int o = 1; o < 8; o <<= 1) {
            int q = __shfl_up_sync(0xff, u, o);
            if (threadIdx.x >= o) u += q;
        }
        ws[threadIdx.x] = u;
    }
    __syncthreads();
    int excl = s - v + (wid ? ws[wid - 1] : 0);
    if (i < Nn) g_off[i] = g_boff[blockIdx.x] + excl;
}

__global__ void k_scatter(const int* __restrict__ src, const int* __restrict__ dst) {
    int e = blockIdx.x * blockDim.x + threadIdx.x;
    if (e < Ee) {
        int s = src[e], d = dst[e];
        int p = atomicAdd(&g_cur[d], 1);
        int idx = g_off[d] + p;
        float w = g_dinv[s] * g_dinv[d];
        g_sw[idx] = make_int2(s, __float_as_int(w));
    }
}

// c_L[j] = gamma_L[j];  c_H[j] = (-1)^j * sum_{k>=j} gamma_H[k] * C(k,j)
__global__ void k_coeff(const float* __restrict__ gL, const float* __restrict__ gH) {
    if (threadIdx.x == 0 && blockIdx.x == 0) {
        double C[KK + 1][KK + 1];
        for (int k = 0; k <= KK; k++)
            for (int j = 0; j <= KK; j++) C[k][j] = 0.0;
        for (int k = 0; k <= KK; k++) {
            C[k][0] = 1.0; C[k][k] = 1.0;
            for (int j = 1; j < k; j++) C[k][j] = C[k - 1][j - 1] + C[k - 1][j];
        }
        for (int j = 0; j <= KK; j++) {
            double s = 0.0;
            for (int k = j; k <= KK; k++) s += (double)gH[k] * C[k][j];
            g_cH[j] = (j & 1) ? (float)(-s) : (float)s;
            g_cL[j] = gL[j];
        }
    }
}

// --------------------------- tiled fp32 GEMM (f32x2 inner) -------------------
// C[M,128] = A[M,KDIM] @ B[KDIM,128] + bias. BM=64, BN=128, BK=16,
// 256 threads, 4x8 micro-tile, packed fma.rn.f32x2.
// As is stored PRE-DUPLICATED as (a,a) 64-bit values so the inner loop has
// zero pack movs.
template <int KDIM>
__global__ __launch_bounds__(256)
void k_gemm1(const float* __restrict__ A, const float* __restrict__ B,
             const float* __restrict__ bias, float* __restrict__ C, int M) {
    __shared__ __align__(16) unsigned long long As[64][17];
    __shared__ __align__(16) float Bs[16][132];
    int tid = threadIdx.x;
    int tx = tid & 15, ty = tid >> 4;
    int row0 = blockIdx.x * 64;
    unsigned long long acc2[4][4];
#pragma unroll
    for (int i = 0; i < 4; i++)
#pragma unroll
        for (int j = 0; j < 4; j++) acc2[i][j] = 0ull;

    for (int k0 = 0; k0 < KDIM; k0 += 16) {
#pragma unroll
        for (int i = tid; i < 64 * 16; i += 256) {
            int r = i >> 4, c = i & 15;
            int gr = row0 + r, gc = k0 + c;
            float v = (gr < M && gc < KDIM) ? A[(size_t)gr * KDIM + gc] : 0.f;
            As[r][c] = pack2(v, v);
        }
#pragma unroll
        for (int i = tid; i < 16 * 128; i += 256) {
            int r = i >> 7, c = i & 127;
            int gk = k0 + r;
            Bs[r][c] = (gk < KDIM) ? B[(size_t)gk * 128 + c] : 0.f;
        }
        __syncthreads();
#pragma unroll
        for (int k = 0; k < 16; k++) {
            const ulonglong2* brow = (const ulonglong2*)&Bs[k][tx * 8];
            ulonglong2 q0 = brow[0];   // (b0,b1) (b2,b3)
            ulonglong2 q1 = brow[1];   // (b4,b5) (b6,b7)
#pragma unroll
            for (int i = 0; i < 4; i++) {
                unsigned long long aa = As[ty * 4 + i][k];
                FMA2(acc2[i][0], aa, q0.x, acc2[i][0]);
                FMA2(acc2[i][1], aa, q0.y, acc2[i][1]);
                FMA2(acc2[i][2], aa, q1.x, acc2[i][2]);
                FMA2(acc2[i][3], aa, q1.y, acc2[i][3]);
            }
        }
        __syncthreads();
    }
#pragma unroll
    for (int i = 0; i < 4; i++) {
        int gr = row0 + ty * 4 + i;
        if (gr < M) {
#pragma unroll
            for (int j = 0; j < 4; j++) {
                float lo, hi;
                unpack2(acc2[i][j], lo, hi);
                int gc = tx * 8 + 2 * j;
                C[(size_t)gr * 128 + gc]     = lo + bias[gc];
                C[(size_t)gr * 128 + gc + 1] = hi + bias[gc + 1];
            }
        }
    }
}

// Epilogue GEMM: both branches in one launch (blockIdx.y = branch).
// C = relu((A*alpha + beta) @ W_up + b_up), K = 128.
__global__ __launch_bounds__(256)
void k_gemm_ep(const float* __restrict__ AL, const float* __restrict__ AH,
               const float* __restrict__ B, const float* __restrict__ bias,
               float* __restrict__ out, int M) {
    __shared__ __align__(16) unsigned long long As[64][17];
    __shared__ __align__(16) float Bs[16][132];
    int br = blockIdx.y;
    const float* __restrict__ A = br ? AH : AL;
    const float* __restrict__ alpha = g_alpha + br * HIDF;
    const float* __restrict__ beta  = g_beta  + br * HIDF;
    float* __restrict__ C = out + (size_t)br * Nn * HIDF;

    int tid = threadIdx.x;
    int tx = tid & 15, ty = tid >> 4;
    int row0 = blockIdx.x * 64;
    unsigned long long acc2[4][4];
#pragma unroll
    for (int i = 0; i < 4; i++)
#pragma unroll
        for (int j = 0; j < 4; j++) acc2[i][j] = 0ull;

    for (int k0 = 0; k0 < HIDF; k0 += 16) {
#pragma unroll
        for (int i = tid; i < 64 * 16; i += 256) {
            int r = i >> 4, c = i & 15;
            int gr = row0 + r, gc = k0 + c;
            float v = 0.f;
            if (gr < M) v = fmaf(A[(size_t)gr * HIDF + gc], alpha[gc], beta[gc]);
            As[r][c] = pack2(v, v);
        }
#pragma unroll
        for (int i = tid; i < 16 * 128; i += 256) {
            int r = i >> 7, c = i & 127;
            Bs[r][c] = B[(size_t)(k0 + r) * 128 + c];
        }
        __syncthreads();
#pragma unroll
        for (int k = 0; k < 16; k++) {
            const ulonglong2* brow = (const ulonglong2*)&Bs[k][tx * 8];
            ulonglong2 q0 = brow[0];
            ulonglong2 q1 = brow[1];
#pragma unroll
            for (int i = 0; i < 4; i++) {
                unsigned long long aa = As[ty * 4 + i][k];
                FMA2(acc2[i][0], aa, q0.x, acc2[i][0]);
                FMA2(acc2[i][1], aa, q0.y, acc2[i][1]);
                FMA2(acc2[i][2], aa, q1.x, acc2[i][2]);
                FMA2(acc2[i][3], aa, q1.y, acc2[i][3]);
            }
        }
        __syncthreads();
    }
#pragma unroll
    for (int i = 0; i < 4; i++) {
        int gr = row0 + ty * 4 + i;
        if (gr < M) {
#pragma unroll
            for (int j = 0; j < 4; j++) {
                float lo, hi;
                unpack2(acc2[i][j], lo, hi);
                int gc = tx * 8 + 2 * j;
                C[(size_t)gr * 128 + gc]     = fmaxf(lo + bias[gc], 0.f);
                C[(size_t)gr * 128 + gc + 1] = fmaxf(hi + bias[gc + 1], 0.f);
            }
        }
    }
}

// --------------------------- sparse propagation ------------------------------
// one warp per dst node; each lane owns a float4 (4 features). p_j = A p_{j-1}.
// Edge meta loaded lane-uniform (broadcast LDG.64); 8 gathers in flight.
__global__ __launch_bounds__(256)
void k_prop(int j) {
    int node = blockIdx.x * 8 + (threadIdx.x >> 5);
    if (node >= Nn) return;
    int lane = threadIdx.x & 31;
    const float4* __restrict__ tin = (const float4*)g_P[j - 1];
    float4* __restrict__ tout = (float4*)g_P[j];
    int beg = g_off[node], end = g_off[node + 1];
    float sx = 0.f, sy = 0.f, sz = 0.f, sw = 0.f;
    int e = beg;
    for (; e + 8 <= end; e += 8) {
        int2 a0 = g_sw[e],     a1 = g_sw[e + 1];
        int2 a2 = g_sw[e + 2], a3 = g_sw[e + 3];
        int2 a4 = g_sw[e + 4], a5 = g_sw[e + 5];
        int2 a6 = g_sw[e + 6], a7 = g_sw[e + 7];
        float4 v0 = __ldg(&tin[a0.x * 32 + lane]);
        float4 v1 = __ldg(&tin[a1.x * 32 + lane]);
        float4 v2 = __ldg(&tin[a2.x * 32 + lane]);
        float4 v3 = __ldg(&tin[a3.x * 32 + lane]);
        float4 v4 = __ldg(&tin[a4.x * 32 + lane]);
        float4 v5 = __ldg(&tin[a5.x * 32 + lane]);
        float4 v6 = __ldg(&tin[a6.x * 32 + lane]);
        float4 v7 = __ldg(&tin[a7.x * 32 + lane]);
        float w0 = __int_as_float(a0.y), w1 = __int_as_float(a1.y);
        float w2 = __int_as_float(a2.y), w3 = __int_as_float(a3.y);
        float w4 = __int_as_float(a4.y), w5 = __int_as_float(a5.y);
        float w6 = __int_as_float(a6.y), w7 = __int_as_float(a7.y);
        sx = fmaf(w0, v0.x, sx); sy = fmaf(w0, v0.y, sy);
        sz = fmaf(w0, v0.z, sz); sw = fmaf(w0, v0.w, sw);
        sx = fmaf(w1, v1.x, sx); sy = fmaf(w1, v1.y, sy);
        sz = fmaf(w1, v1.z, sz); sw = fmaf(w1, v1.w, sw);
        sx = fmaf(w2, v2.x, sx); sy = fmaf(w2, v2.y, sy);
        sz = fmaf(w2, v2.z, sz); sw = fmaf(w2, v2.w, sw);
        sx = fmaf(w3, v3.x, sx); sy = fmaf(w3, v3.y, sy);
        sz = fmaf(w3, v3.z, sz); sw = fmaf(w3, v3.w, sw);
        sx = fmaf(w4, v4.x, sx); sy = fmaf(w4, v4.y, sy);
        sz = fmaf(w4, v4.z, sz); sw = fmaf(w4, v4.w, sw);
        sx = fmaf(w5, v5.x, sx); sy = fmaf(w5, v5.y, sy);
        sz = fmaf(w5, v5.z, sz); sw = fmaf(w5, v5.w, sw);
        sx = fmaf(w6, v6.x, sx); sy = fmaf(w6, v6.y, sy);
        sz = fmaf(w6, v6.z, sz); sw = fmaf(w6, v6.w, sw);
        sx = fmaf(w7, v7.x, sx); sy = fmaf(w7, v7.y, sy);
        sz = fmaf(w7, v7.z, sz); sw = fmaf(w7, v7.w, sw);
    }
    for (; e < end; e++) {
        int2 a0 = g_sw[e];
        float w0 = __int_as_float(a0.y);
        float4 v0 = __ldg(&tin[a0.x * 32 + lane]);
        sx = fmaf(w0, v0.x, sx); sy = fmaf(w0, v0.y, sy);
        sz = fmaf(w0, v0.z, sz); sw = fmaf(w0, v0.w, sw);
    }
    tout[node * 32 + lane] = make_float4(sx, sy, sz, sw);
}

// --------------------------- combine + BN partials ---------------------------
__global__ __launch_bounds__(256)
void k_combine() {
    int tid = threadIdx.x;
    int fq = tid & 31;         // feature quad: features 4*fq .. 4*fq+3
    int wid = tid >> 5;
    float cl[KK + 1], ch[KK + 1];
#pragma unroll
    for (int j = 0; j <= KK; j++) { cl[j] = g_cL[j]; ch[j] = g_cH[j]; }

    float4 psL = {0, 0, 0, 0}, pqL = {0, 0, 0, 0};
    float4 psH = {0, 0, 0, 0}, pqH = {0, 0, 0, 0};

    for (int node = blockIdx.x * 8 + wid; node < Nn; node += gridDim.x * 8) {
        int base = node * 32 + fq;
        float4 aL = {0, 0, 0, 0}, aH = {0, 0, 0, 0};
#pragma unroll
        for (int j = 0; j <= KK; j++) {
            float4 p = ((const float4*)g_P[j])[base];
            aL.x = fmaf(cl[j], p.x, aL.x); aL.y = fmaf(cl[j], p.y, aL.y);
            aL.z = fmaf(cl[j], p.z, aL.z); aL.w = fmaf(cl[j], p.w, aL.w);
            aH.x = fmaf(ch[j], p.x, aH.x); aH.y = fmaf(ch[j], p.y, aH.y);
            aH.z = fmaf(ch[j], p.z, aH.z); aH.w = fmaf(ch[j], p.w, aH.w);
        }
        ((float4*)g_accL)[base] = aL;
        ((float4*)g_accH)[base] = aH;
        psL.x += aL.x; psL.y += aL.y; psL.z += aL.z; psL.w += aL.w;
        pqL.x = fmaf(aL.x, aL.x, pqL.x); pqL.y = fmaf(aL.y, aL.y, pqL.y);
        pqL.z = fmaf(aL.z, aL.z, pqL.z); pqL.w = fmaf(aL.w, aL.w, pqL.w);
        psH.x += aH.x; psH.y += aH.y; psH.z += aH.z; psH.w += aH.w;
        pqH.x = fmaf(aH.x, aH.x, pqH.x); pqH.y = fmaf(aH.y, aH.y, pqH.y);
        pqH.z = fmaf(aH.z, aH.z, pqH.z); pqH.w = fmaf(aH.w, aH.w, pqH.w);
    }

    __shared__ float4 sh[4][256];
    sh[0][tid] = psL; sh[1][tid] = pqL; sh[2][tid] = psH; sh[3][tid] = pqH;
    __syncthreads();
    if (tid < 32) {
        float4 a0 = sh[0][tid], a1 = sh[1][tid], a2 = sh[2][tid], a3 = sh[3][tid];
#pragma unroll
        for (int w = 1; w < 8; w++) {
            float4 t;
            t = sh[0][tid + 32 * w]; a0.x += t.x; a0.y += t.y; a0.z += t.z; a0.w += t.w;
            t = sh[1][tid + 32 * w]; a1.x += t.x; a1.y += t.y; a1.z += t.z; a1.w += t.w;
            t = sh[2][tid + 32 * w]; a2.x += t.x; a2.y += t.y; a2.z += t.z; a2.w += t.w;
            t = sh[3][tid + 32 * w]; a3.x += t.x; a3.y += t.y; a3.z += t.z; a3.w += t.w;
        }
        int f = tid * 4;
        atomicAdd(&g_sum[0 * HIDF + f + 0], a0.x); atomicAdd(&g_sum[0 * HIDF + f + 1], a0.y);
        atomicAdd(&g_sum[0 * HIDF + f + 2], a0.z); atomicAdd(&g_sum[0 * HIDF + f + 3], a0.w);
        atomicAdd(&g_sum[1 * HIDF + f + 0], a1.x); atomicAdd(&g_sum[1 * HIDF + f + 1], a1.y);
        atomicAdd(&g_sum[1 * HIDF + f + 2], a1.z); atomicAdd(&g_sum[1 * HIDF + f + 3], a1.w);
        atomicAdd(&g_sum[2 * HIDF + f + 0], a2.x); atomicAdd(&g_sum[2 * HIDF + f + 1], a2.y);
        atomicAdd(&g_sum[2 * HIDF + f + 2], a2.z); atomicAdd(&g_sum[2 * HIDF + f + 3], a2.w);
        atomicAdd(&g_sum[3 * HIDF + f + 0], a3.x); atomicAdd(&g_sum[3 * HIDF + f + 1], a3.y);
        atomicAdd(&g_sum[3 * HIDF + f + 2], a3.z); atomicAdd(&g_sum[3 * HIDF + f + 3], a3.w);
    }
}

__global__ void k_bnfinal(const float* __restrict__ bn_scale,
                          const float* __restrict__ bn_shift) {
    int f = threadIdx.x;
    if (f < HIDF) {
        const float invN = 1.f / (float)Nn;
        float mu = g_sum[f] * invN;
        float var = g_sum[HIDF + f] * invN - mu * mu;
        float a = rsqrtf(var + 1e-5f) * bn_scale[f];
        g_alpha[f] = a;
        g_beta[f] = bn_shift[f] - mu * a;
        mu = g_sum[2 * HIDF + f] * invN;
        var = g_sum[3 * HIDF + f] * invN - mu * mu;
        a = rsqrtf(var + 1e-5f) * bn_scale[f];
        g_alpha[HIDF + f] = a;
        g_beta[HIDF + f] = bn_shift[f] - mu * a;
    }
}

// ------------------------------- launcher ------------------------------------
extern "C" void kernel_launch(void* const* d_in, const int* in_sizes, int n_in,
                              void* d_out, int out_size) {
    const float* x    = (const float*)d_in[0];
    const int*   ei   = (const int*)d_in[1];
    const float* W_in = (const float*)d_in[2];
    const float* b_in = (const float*)d_in[3];
    const float* gL   = (const float*)d_in[4];
    const float* gH   = (const float*)d_in[5];
    const float* bns  = (const float*)d_in[6];
    const float* bnb  = (const float*)d_in[7];
    const float* W_up = (const float*)d_in[8];
    const float* b_up = (const float*)d_in[9];
    float* out = (float*)d_out;

    const int* src = ei;
    const int* dst = ei + Ee;

    void *pP, *pAL, *pAH;
    cudaGetSymbolAddress(&pP,  g_P);
    cudaGetSymbolAddress(&pAL, g_accL);
    cudaGetSymbolAddress(&pAH, g_accH);
    float* P0   = (float*)pP;                  // g_P[0]
    float* accL = (float*)pAL;
    float* accH = (float*)pAH;

    const int nblkN = (Nn + 255) / 256;   // 196
    const int nblkE = (Ee + 255) / 256;   // 3125
    const int gemmB = (Nn + 63) / 64;     // 782

    k_init<<<nblkN, 256>>>();
    k_deg<<<nblkE, 256>>>(dst);
    k_blocksum<<<nblkN, 256>>>();
    k_scanb<<<1, 256>>>(nblkN);
    k_scanwrite<<<nblkN, 256>>>();
    k_scatter<<<nblkE, 256>>>(src, dst);
    k_coeff<<<1, 32>>>(gL, gH);

    // p_0 = h = x @ W_in + b_in
    k_gemm1<INF_><<<gemmB, 256>>>(x, W_in, b_in, P0, Nn);

    // Krylov chain p_j = A p_{j-1}
    for (int j = 1; j <= KK; j++)
        k_prop<<<(Nn + 7) / 8, 256>>>(j);

    // acc_L / acc_H + BN statistics
    k_combine<<<592, 256>>>();
    k_bnfinal<<<1, 128>>>(bns, bnb);

    // Z = relu(BN(acc) @ W_up + b_up), both branches in one launch
    dim3 epg(gemmB, 2);
    k_gemm_ep<<<epg, 256>>>(accL, accH, W_up, b_up, out, Nn);
}

// round 11
// speedup vs baseline: 1.1098x; 1.0779x over previous
#include <cuda_runtime.h>
#include <cuda_bf16.h>
#include <cstdint>
#include <cstdio>

#define Nn   50000
#define Ee   800000
#define INF_ 500
#define HIDF 128
#define KK   10     // K (polynomial order); K+1 = 11 coefficients

// ------------------------- device scratch (static, no allocs) ---------------
__device__ int   g_deg[Nn];
__device__ int   g_cur[Nn];
__device__ int   g_off[Nn + 1];
__device__ float g_dinv[Nn];
__device__ int2  g_sw[Ee];                         // packed {src, __float_as_int(w)}
__device__ int   g_bsum[256];
__device__ int   g_boff[256];
__device__ float g_P[KK + 1][(size_t)Nn * HIDF];   // Krylov basis p_j = A^j h  (~282 MB)
__device__ float g_accL[(size_t)Nn * HIDF];
__device__ float g_accH[(size_t)Nn * HIDF];
__device__ float g_sum[4 * HIDF];                  // sumL, sqL, sumH, sqH
__device__ float g_cL[KK + 1];
__device__ float g_cH[KK + 1];
__device__ float g_alpha[2 * HIDF];                // per-branch BN scale  (L then H)
__device__ float g_beta[2 * HIDF];                 // per-branch BN shift

// ------------------------- f32x2 packed-FMA helpers --------------------------
__device__ __forceinline__ unsigned long long pack2(float lo, float hi) {
    unsigned long long r;
    asm("mov.b64 %0, {%1, %2};" : "=l"(r) : "f"(lo), "f"(hi));
    return r;
}
__device__ __forceinline__ void unpack2(unsigned long long p, float& lo, float& hi) {
    asm("mov.b64 {%0, %1}, %2;" : "=f"(lo), "=f"(hi) : "l"(p));
}
#define FMA2(d, a, b, c) \
    asm("fma.rn.f32x2 %0, %1, %2, %3;" : "=l"(d) : "l"(a), "l"(b), "l"(c))

// m16n8k16 bf16 MMA, fp32 accumulate (standard sm_80+ PTX; compiles on sm_103)
#define MMA_BF16(d, a, b0, b1) \
    asm volatile("mma.sync.aligned.m16n8k16.row.col.f32.bf16.bf16.f32 " \
        "{%0,%1,%2,%3}, {%4,%5,%6,%7}, {%8,%9}, {%0,%1,%2,%3};" \
        : "+f"((d)[0]), "+f"((d)[1]), "+f"((d)[2]), "+f"((d)[3]) \
        : "r"((a)[0]), "r"((a)[1]), "r"((a)[2]), "r"((a)[3]), "r"(b0), "r"(b1))

// ------------------------------- small kernels -------------------------------
__global__ void k_init() {
    int i = blockIdx.x * blockDim.x + threadIdx.x;
    if (i < Nn) { g_deg[i] = 0; g_cur[i] = 0; }
    if (i < 4 * HIDF) g_sum[i] = 0.f;
    if (i == 0) g_off[Nn] = Ee;
}

__global__ void k_deg(const int* __restrict__ dst) {
    int e = blockIdx.x * blockDim.x + threadIdx.x;
    if (e < Ee) atomicAdd(&g_deg[dst[e]], 1);
}

__global__ void k_dinv() {
    int i = blockIdx.x * blockDim.x + threadIdx.x;
    if (i < Nn) g_dinv[i] = rsqrtf(fmaxf((float)g_deg[i], 1.f));
}

// ------------- multi-block exclusive scan of g_deg -> g_off ------------------
__global__ void k_blocksum() {
    int i = blockIdx.x * 256 + threadIdx.x;
    int v = (i < Nn) ? g_deg[i] : 0;
#pragma unroll
    for (int o = 16; o; o >>= 1) v += __shfl_down_sync(~0u, v, o);
    __shared__ int ws[8];
    if ((threadIdx.x & 31) == 0) ws[threadIdx.x >> 5] = v;
    __syncthreads();
    if (threadIdx.x < 8) {
        int t = ws[threadIdx.x];
#pragma unroll
        for (int o = 4; o; o >>= 1) t += __shfl_down_sync(0xff, t, o);
        if (threadIdx.x == 0) g_bsum[blockIdx.x] = t;
    }
}

__global__ void k_scanb(int nb) {   // single block; exclusive scan of block sums
    int t = threadIdx.x;
    int lane = t & 31, wid = t >> 5;
    int v = (t < nb) ? g_bsum[t] : 0;
    int s = v;
#pragma unroll
    for (int o = 1; o < 32; o <<= 1) {
        int u = __shfl_up_sync(~0u, s, o);
        if (lane >= o) s += u;
    }
    __shared__ int ws[8];
    if (lane == 31) ws[wid] = s;
    __syncthreads();
    if (t < 8) {
        int u = ws[t];
#pragma unroll
        for (int o = 1; o < 8; o <<= 1) {
            int q = __shfl_up_sync(0xff, u, o);
            if (t >= o) u += q;
        }
        ws[t] = u;
    }
    __syncthreads();
    int excl = s - v + (wid ? ws[wid - 1] : 0);
    if (t < nb) g_boff[t] = excl;
}

__global__ void k_scanwrite() {
    int i = blockIdx.x * 256 + threadIdx.x;
    int lane = threadIdx.x & 31, wid = threadIdx.x >> 5;
    int v = (i < Nn) ? g_deg[i] : 0;
    int s = v;
#pragma unroll
    for (int o = 1; o < 32; o <<= 1) {
        int u = __shfl_up_sync(~0u, s, o);
        if (lane >= o) s += u;
    }
    __shared__ int ws[8];
    if (lane == 31) ws[wid] = s;
    __syncthreads();
    if (threadIdx.x < 8) {
        int u = ws[threadIdx.x];
#pragma unroll
        for (int o = 1; o < 8; o <<= 1) {
            int q = __shfl_up_sync(0xff, u, o);
            if (threadIdx.x >= o) u += q;
        }
        ws[threadIdx.x] = u;
    }
    __syncthreads();
    int excl = s - v + (wid ? ws[wid - 1] : 0);
    if (i < Nn) g_off[i] = g_boff[blockIdx.x] + excl;
}

__global__ void k_scatter(const int* __restrict__ src, const int* __restrict__ dst) {
    int e = blockIdx.x * blockDim.x + threadIdx.x;
    if (e < Ee) {
        int s = src[e], d = dst[e];
        int p = atomicAdd(&g_cur[d], 1);
        int idx = g_off[d] + p;
        float w = g_dinv[s] * g_dinv[d];
        g_sw[idx] = make_int2(s, __float_as_int(w));
    }
}

// c_L[j] = gamma_L[j];  c_H[j] = (-1)^j * sum_{k>=j} gamma_H[k] * C(k,j)
__global__ void k_coeff(const float* __restrict__ gL, const float* __restrict__ gH) {
    if (threadIdx.x == 0 && blockIdx.x == 0) {
        double C[KK + 1][KK + 1];
        for (int k = 0; k <= KK; k++)
            for (int j = 0; j <= KK; j++) C[k][j] = 0.0;
        for (int k = 0; k <= KK; k++) {
            C[k][0] = 1.0; C[k][k] = 1.0;
            for (int j = 1; j < k; j++) C[k][j] = C[k - 1][j - 1] + C[k - 1][j];
        }
        for (int j = 0; j <= KK; j++) {
            double s = 0.0;
            for (int k = j; k <= KK; k++) s += (double)gH[k] * C[k][j];
            g_cH[j] = (j & 1) ? (float)(-s) : (float)s;
            g_cL[j] = gL[j];
        }
    }
}

// --------------------- GEMM1 via mma.sync bf16 (3-term split) ---------------
// C[Nn,128] = x[Nn,500] @ W[500,128] + bias.
// x = xh + xl, W = Wh + Wl (bf16 hi/lo), acc += xh*Wh + xh*Wl + xl*Wh (fp32).
// Block tile 64(M) x 128(N), 8 warps in 2x4 grid, warp tile 32x32,
// K chunks of 32 (16 chunks; tail zero-padded).
#define ASTR 34   // smem row stride in bf16 elements (68B, 4B-aligned)

__global__ __launch_bounds__(256)
void k_gemm1_mma(const float* __restrict__ A, const float* __restrict__ B,
                 const float* __restrict__ bias, float* __restrict__ C, int M) {
    __shared__ __nv_bfloat16 Ash[64][ASTR], Asl[64][ASTR];
    __shared__ __nv_bfloat16 Bsh[128][ASTR], Bsl[128][ASTR];
    int tid = threadIdx.x;
    int w = tid >> 5, lane = tid & 31;
    int g = lane >> 2, tig = lane & 3;
    int wm = w & 1, wn = w >> 1;          // warp grid 2(M) x 4(N)
    int row0 = blockIdx.x * 64;

    float acc[2][4][4];
#pragma unroll
    for (int mt = 0; mt < 2; mt++)
#pragma unroll
        for (int nf = 0; nf < 4; nf++)
#pragma unroll
            for (int i = 0; i < 4; i++) acc[mt][nf][i] = 0.f;

    for (int ch = 0; ch < 16; ch++) {
        int k0 = ch * 32;
        // ---- load A chunk: 64 rows x 32 cols fp32 -> bf16 hi/lo ----
        {
            int r = tid >> 2, c0 = (tid & 3) * 8;
            int gr = row0 + r;
#pragma unroll
            for (int i = 0; i < 8; i++) {
                int gc = k0 + c0 + i;
                float v = (gr < M && gc < INF_) ? A[(size_t)gr * INF_ + gc] : 0.f;
                __nv_bfloat16 h = __float2bfloat16(v);
                __nv_bfloat16 l = __float2bfloat16(v - __bfloat162float(h));
                Ash[r][c0 + i] = h;
                Asl[r][c0 + i] = l;
            }
        }
        // ---- load B chunk transposed: Bs[n][kk] = W[k0+kk][n] ----
        {
            int kk = tid >> 3, n0 = (tid & 7) * 16;
            int gk = k0 + kk;
#pragma unroll
            for (int i = 0; i < 16; i++) {
                float v = (gk < INF_) ? B[(size_t)gk * HIDF + n0 + i] : 0.f;
                __nv_bfloat16 h = __float2bfloat16(v);
                __nv_bfloat16 l = __float2bfloat16(v - __bfloat162float(h));
                Bsh[n0 + i][kk] = h;
                Bsl[n0 + i][kk] = l;
            }
        }
        __syncthreads();

#pragma unroll
        for (int ks = 0; ks < 2; ks++) {
            int kb = ks * 16;
            uint32_t ah[2][4], al[2][4];
#pragma unroll
            for (int mt = 0; mt < 2; mt++) {
                int r = wm * 32 + mt * 16 + g;
                int c = kb + tig * 2;
                ah[mt][0] = *(const uint32_t*)&Ash[r][c];
                ah[mt][1] = *(const uint32_t*)&Ash[r + 8][c];
                ah[mt][2] = *(const uint32_t*)&Ash[r][c + 8];
                ah[mt][3] = *(const uint32_t*)&Ash[r + 8][c + 8];
                al[mt][0] = *(const uint32_t*)&Asl[r][c];
                al[mt][1] = *(const uint32_t*)&Asl[r + 8][c];
                al[mt][2] = *(const uint32_t*)&Asl[r][c + 8];
                al[mt][3] = *(const uint32_t*)&Asl[r + 8][c + 8];
            }
#pragma unroll
            for (int nf = 0; nf < 4; nf++) {
                int n = wn * 32 + nf * 8 + g;
                uint32_t bh0 = *(const uint32_t*)&Bsh[n][kb + tig * 2];
                uint32_t bh1 = *(const uint32_t*)&Bsh[n][kb + tig * 2 + 8];
                uint32_t bl0 = *(const uint32_t*)&Bsl[n][kb + tig * 2];
                uint32_t bl1 = *(const uint32_t*)&Bsl[n][kb + tig * 2 + 8];
#pragma unroll
                for (int mt = 0; mt < 2; mt++) {
                    MMA_BF16(acc[mt][nf], ah[mt], bh0, bh1);
                    MMA_BF16(acc[mt][nf], ah[mt], bl0, bl1);
                    MMA_BF16(acc[mt][nf], al[mt], bh0, bh1);
                }
            }
        }
        __syncthreads();
    }

    // ---- epilogue: c0,c1 -> (g, 2t, 2t+1); c2,c3 -> (g+8, ...) ----
#pragma unroll
    for (int mt = 0; mt < 2; mt++) {
#pragma unroll
        for (int nf = 0; nf < 4; nf++) {
            int col = wn * 32 + nf * 8 + tig * 2;
            int gr0 = row0 + wm * 32 + mt * 16 + g;
            int gr1 = gr0 + 8;
            if (gr0 < M) {
                C[(size_t)gr0 * HIDF + col]     = acc[mt][nf][0] + bias[col];
                C[(size_t)gr0 * HIDF + col + 1] = acc[mt][nf][1] + bias[col + 1];
            }
            if (gr1 < M) {
                C[(size_t)gr1 * HIDF + col]     = acc[mt][nf][2] + bias[col];
                C[(size_t)gr1 * HIDF + col + 1] = acc[mt][nf][3] + bias[col + 1];
            }
        }
    }
}

// Epilogue GEMM: both branches in one launch (blockIdx.y = branch).
// C = relu((A*alpha + beta) @ W_up + b_up), K = 128.  (866-proven f32x2 form)
__global__ __launch_bounds__(256)
void k_gemm_ep(const float* __restrict__ AL, const float* __restrict__ AH,
               const float* __restrict__ B, const float* __restrict__ bias,
               float* __restrict__ out, int M) {
    __shared__ __align__(16) float As[64][17];
    __shared__ __align__(16) float Bs[16][132];
    int br = blockIdx.y;
    const float* __restrict__ A = br ? AH : AL;
    const float* __restrict__ alpha = g_alpha + br * HIDF;
    const float* __restrict__ beta  = g_beta  + br * HIDF;
    float* __restrict__ C = out + (size_t)br * Nn * HIDF;

    int tid = threadIdx.x;
    int tx = tid & 15, ty = tid >> 4;
    int row0 = blockIdx.x * 64;
    unsigned long long acc2[4][4];
#pragma unroll
    for (int i = 0; i < 4; i++)
#pragma unroll
        for (int j = 0; j < 4; j++) acc2[i][j] = 0ull;

    for (int k0 = 0; k0 < HIDF; k0 += 16) {
#pragma unroll
        for (int i = tid; i < 64 * 16; i += 256) {
            int r = i >> 4, c = i & 15;
            int gr = row0 + r, gc = k0 + c;
            float v = 0.f;
            if (gr < M) v = fmaf(A[(size_t)gr * HIDF + gc], alpha[gc], beta[gc]);
            As[r][c] = v;
        }
#pragma unroll
        for (int i = tid; i < 16 * 128; i += 256) {
            int r = i >> 7, c = i & 127;
            Bs[r][c] = B[(size_t)(k0 + r) * 128 + c];
        }
        __syncthreads();
#pragma unroll
        for (int k = 0; k < 16; k++) {
            const ulonglong2* brow = (const ulonglong2*)&Bs[k][tx * 8];
            ulonglong2 q0 = brow[0];
            ulonglong2 q1 = brow[1];
#pragma unroll
            for (int i = 0; i < 4; i++) {
                float a = As[ty * 4 + i][k];
                unsigned long long aa = pack2(a, a);
                FMA2(acc2[i][0], aa, q0.x, acc2[i][0]);
                FMA2(acc2[i][1], aa, q0.y, acc2[i][1]);
                FMA2(acc2[i][2], aa, q1.x, acc2[i][2]);
                FMA2(acc2[i][3], aa, q1.y, acc2[i][3]);
            }
        }
        __syncthreads();
    }
#pragma unroll
    for (int i = 0; i < 4; i++) {
        int gr = row0 + ty * 4 + i;
        if (gr < M) {
#pragma unroll
            for (int j = 0; j < 4; j++) {
                float lo, hi;
                unpack2(acc2[i][j], lo, hi);
                int gc = tx * 8 + 2 * j;
                C[(size_t)gr * 128 + gc]     = fmaxf(lo + bias[gc], 0.f);
                C[(size_t)gr * 128 + gc + 1] = fmaxf(hi + bias[gc + 1], 0.f);
            }
        }
    }
}

// --------------------------- sparse propagation (866-proven) -----------------
__global__ __launch_bounds__(256)
void k_prop(int j) {
    int node = blockIdx.x * 8 + (threadIdx.x >> 5);
    if (node >= Nn) return;
    int lane = threadIdx.x & 31;
    const float4* __restrict__ tin = (const float4*)g_P[j - 1];
    float4* __restrict__ tout = (float4*)g_P[j];
    int beg = g_off[node], end = g_off[node + 1];
    float sx = 0.f, sy = 0.f, sz = 0.f, sw = 0.f;
    int e = beg;
    for (; e + 4 <= end; e += 4) {
        int2 a0 = g_sw[e],     a1 = g_sw[e + 1];
        int2 a2 = g_sw[e + 2], a3 = g_sw[e + 3];
        float4 v0 = __ldg(&tin[a0.x * 32 + lane]);
        float4 v1 = __ldg(&tin[a1.x * 32 + lane]);
        float4 v2 = __ldg(&tin[a2.x * 32 + lane]);
        float4 v3 = __ldg(&tin[a3.x * 32 + lane]);
        float w0 = __int_as_float(a0.y), w1 = __int_as_float(a1.y);
        float w2 = __int_as_float(a2.y), w3 = __int_as_float(a3.y);
        sx = fmaf(w0, v0.x, sx); sy = fmaf(w0, v0.y, sy);
        sz = fmaf(w0, v0.z, sz); sw = fmaf(w0, v0.w, sw);
        sx = fmaf(w1, v1.x, sx); sy = fmaf(w1, v1.y, sy);
        sz = fmaf(w1, v1.z, sz); sw = fmaf(w1, v1.w, sw);
        sx = fmaf(w2, v2.x, sx); sy = fmaf(w2, v2.y, sy);
        sz = fmaf(w2, v2.z, sz); sw = fmaf(w2, v2.w, sw);
        sx = fmaf(w3, v3.x, sx); sy = fmaf(w3, v3.y, sy);
        sz = fmaf(w3, v3.z, sz); sw = fmaf(w3, v3.w, sw);
    }
    for (; e < end; e++) {
        int2 a0 = g_sw[e];
        float w0 = __int_as_float(a0.y);
        float4 v0 = __ldg(&tin[a0.x * 32 + lane]);
        sx = fmaf(w0, v0.x, sx); sy = fmaf(w0, v0.y, sy);
        sz = fmaf(w0, v0.z, sz); sw = fmaf(w0, v0.w, sw);
    }
    tout[node * 32 + lane] = make_float4(sx, sy, sz, sw);
}

// --------------------------- combine + BN partials ---------------------------
__global__ __launch_bounds__(256)
void k_combine() {
    int tid = threadIdx.x;
    int fq = tid & 31;
    int wid = tid >> 5;
    float cl[KK + 1], ch[KK + 1];
#pragma unroll
    for (int j = 0; j <= KK; j++) { cl[j] = g_cL[j]; ch[j] = g_cH[j]; }

    float4 psL = {0, 0, 0, 0}, pqL = {0, 0, 0, 0};
    float4 psH = {0, 0, 0, 0}, pqH = {0, 0, 0, 0};

    for (int node = blockIdx.x * 8 + wid; node < Nn; node += gridDim.x * 8) {
        int base = node * 32 + fq;
        float4 aL = {0, 0, 0, 0}, aH = {0, 0, 0, 0};
#pragma unroll
        for (int j = 0; j <= KK; j++) {
            float4 p = ((const float4*)g_P[j])[base];
            aL.x = fmaf(cl[j], p.x, aL.x); aL.y = fmaf(cl[j], p.y, aL.y);
            aL.z = fmaf(cl[j], p.z, aL.z); aL.w = fmaf(cl[j], p.w, aL.w);
            aH.x = fmaf(ch[j], p.x, aH.x); aH.y = fmaf(ch[j], p.y, aH.y);
            aH.z = fmaf(ch[j], p.z, aH.z); aH.w = fmaf(ch[j], p.w, aH.w);
        }
        ((float4*)g_accL)[base] = aL;
        ((float4*)g_accH)[base] = aH;
        psL.x += aL.x; psL.y += aL.y; psL.z += aL.z; psL.w += aL.w;
        pqL.x = fmaf(aL.x, aL.x, pqL.x); pqL.y = fmaf(aL.y, aL.y, pqL.y);
        pqL.z = fmaf(aL.z, aL.z, pqL.z); pqL.w = fmaf(aL.w, aL.w, pqL.w);
        psH.x += aH.x; psH.y += aH.y; psH.z += aH.z; psH.w += aH.w;
        pqH.x = fmaf(aH.x, aH.x, pqH.x); pqH.y = fmaf(aH.y, aH.y, pqH.y);
        pqH.z = fmaf(aH.z, aH.z, pqH.z); pqH.w = fmaf(aH.w, aH.w, pqH.w);
    }

    __shared__ float4 sh[4][256];
    sh[0][tid] = psL; sh[1][tid] = pqL; sh[2][tid] = psH; sh[3][tid] = pqH;
    __syncthreads();
    if (tid < 32) {
        float4 a0 = sh[0][tid], a1 = sh[1][tid], a2 = sh[2][tid], a3 = sh[3][tid];
#pragma unroll
        for (int w = 1; w < 8; w++) {
            float4 t;
            t = sh[0][tid + 32 * w]; a0.x += t.x; a0.y += t.y; a0.z += t.z; a0.w += t.w;
            t = sh[1][tid + 32 * w]; a1.x += t.x; a1.y += t.y; a1.z += t.z; a1.w += t.w;
            t = sh[2][tid + 32 * w]; a2.x += t.x; a2.y += t.y; a2.z += t.z; a2.w += t.w;
            t = sh[3][tid + 32 * w]; a3.x += t.x; a3.y += t.y; a3.z += t.z; a3.w += t.w;
        }
        int f = tid * 4;
        atomicAdd(&g_sum[0 * HIDF + f + 0], a0.x); atomicAdd(&g_sum[0 * HIDF + f + 1], a0.y);
        atomicAdd(&g_sum[0 * HIDF + f + 2], a0.z); atomicAdd(&g_sum[0 * HIDF + f + 3], a0.w);
        atomicAdd(&g_sum[1 * HIDF + f + 0], a1.x); atomicAdd(&g_sum[1 * HIDF + f + 1], a1.y);
        atomicAdd(&g_sum[1 * HIDF + f + 2], a1.z); atomicAdd(&g_sum[1 * HIDF + f + 3], a1.w);
        atomicAdd(&g_sum[2 * HIDF + f + 0], a2.x); atomicAdd(&g_sum[2 * HIDF + f + 1], a2.y);
        atomicAdd(&g_sum[2 * HIDF + f + 2], a2.z); atomicAdd(&g_sum[2 * HIDF + f + 3], a2.w);
        atomicAdd(&g_sum[3 * HIDF + f + 0], a3.x); atomicAdd(&g_sum[3 * HIDF + f + 1], a3.y);
        atomicAdd(&g_sum[3 * HIDF + f + 2], a3.z); atomicAdd(&g_sum[3 * HIDF + f + 3], a3.w);
    }
}

__global__ void k_bnfinal(const float* __restrict__ bn_scale,
                          const float* __restrict__ bn_shift) {
    int f = threadIdx.x;
    if (f < HIDF) {
        const float invN = 1.f / (float)Nn;
        float mu = g_sum[f] * invN;
        float var = g_sum[HIDF + f] * invN - mu * mu;
        float a = rsqrtf(var + 1e-5f) * bn_scale[f];
        g_alpha[f] = a;
        g_beta[f] = bn_shift[f] - mu * a;
        mu = g_sum[2 * HIDF + f] * invN;
        var = g_sum[3 * HIDF + f] * invN - mu * mu;
        a = rsqrtf(var + 1e-5f) * bn_scale[f];
        g_alpha[HIDF + f] = a;
        g_beta[HIDF + f] = bn_shift[f] - mu * a;
    }
}

// ------------------------------- launcher ------------------------------------
extern "C" void kernel_launch(void* const* d_in, const int* in_sizes, int n_in,
                              void* d_out, int out_size) {
    const float* x    = (const float*)d_in[0];
    const int*   ei   = (const int*)d_in[1];
    const float* W_in = (const float*)d_in[2];
    const float* b_in = (const float*)d_in[3];
    const float* gL   = (const float*)d_in[4];
    const float* gH   = (const float*)d_in[5];
    const float* bns  = (const float*)d_in[6];
    const float* bnb  = (const float*)d_in[7];
    const float* W_up = (const float*)d_in[8];
    const float* b_up = (const float*)d_in[9];
    float* out = (float*)d_out;

    const int* src = ei;
    const int* dst = ei + Ee;

    void *pP, *pAL, *pAH;
    cudaGetSymbolAddress(&pP,  g_P);
    cudaGetSymbolAddress(&pAL, g_accL);
    cudaGetSymbolAddress(&pAH, g_accH);
    float* P0   = (float*)pP;                  // g_P[0]
    float* accL = (float*)pAL;
    float* accH = (float*)pAH;

    const int nblkN = (Nn + 255) / 256;   // 196
    const int nblkE = (Ee + 255) / 256;   // 3125
    const int gemmB = (Nn + 63) / 64;     // 782

    k_init<<<nblkN, 256>>>();
    k_deg<<<nblkE, 256>>>(dst);
    k_dinv<<<nblkN, 256>>>();
    k_blocksum<<<nblkN, 256>>>();
    k_scanb<<<1, 256>>>(nblkN);
    k_scanwrite<<<nblkN, 256>>>();
    k_scatter<<<nblkE, 256>>>(src, dst);
    k_coeff<<<1, 32>>>(gL, gH);

    // p_0 = h = x @ W_in + b_in   (tensor-core bf16 3-term split via mma.sync)
    k_gemm1_mma<<<gemmB, 256>>>(x, W_in, b_in, P0, Nn);

    // Krylov chain p_j = A p_{j-1}
    for (int j = 1; j <= KK; j++)
        k_prop<<<(Nn + 7) / 8, 256>>>(j);

    // acc_L / acc_H + BN statistics
    k_combine<<<296, 256>>>();
    k_bnfinal<<<1, 128>>>(bns, bnb);

    // Z = relu(BN(acc) @ W_up + b_up), both branches in one launch
    dim3 epg(gemmB, 2);
    k_gemm_ep<<<epg, 256>>>(accL, accH, W_up, b_up, out, Nn);
}

// round 13
// speedup vs baseline: 1.1536x; 1.0395x over previous
#include <cuda_runtime.h>
#include <cuda_bf16.h>
#include <cstdint>
#include <cstdio>

#define Nn   50000
#define Ee   800000
#define INF_ 500
#define HIDF 128
#define KK   10     // K (polynomial order); K+1 = 11 coefficients

// ------------------------- device scratch (static, no allocs) ---------------
__device__ int   g_deg[Nn];
__device__ int   g_cur[Nn];
__device__ int   g_off[Nn + 1];
__device__ float g_dinv[Nn];
__device__ int2  g_sw[Ee];                         // packed {src, __float_as_int(w)}
__device__ int   g_bsum[256];
__device__ int   g_boff[256];
__device__ float g_P[KK + 1][(size_t)Nn * HIDF];   // Krylov basis p_j = A^j h  (~282 MB)
__device__ float g_accL[(size_t)Nn * HIDF];
__device__ float g_accH[(size_t)Nn * HIDF];
__device__ float g_sum[4 * HIDF];                  // sumL, sqL, sumH, sqH
__device__ float g_cL[KK + 1];
__device__ float g_cH[KK + 1];
__device__ float g_alpha[2 * HIDF];                // per-branch BN scale  (L then H)
__device__ float g_beta[2 * HIDF];                 // per-branch BN shift

// m16n8k16 bf16 MMA, fp32 accumulate (standard sm_80+ PTX; compiles on sm_103)
#define MMA_BF16(d, a, b0, b1) \
    asm volatile("mma.sync.aligned.m16n8k16.row.col.f32.bf16.bf16.f32 " \
        "{%0,%1,%2,%3}, {%4,%5,%6,%7}, {%8,%9}, {%0,%1,%2,%3};" \
        : "+f"((d)[0]), "+f"((d)[1]), "+f"((d)[2]), "+f"((d)[3]) \
        : "r"((a)[0]), "r"((a)[1]), "r"((a)[2]), "r"((a)[3]), "r"(b0), "r"(b1))

// ------------------------------- small kernels -------------------------------
__global__ void k_init() {
    int i = blockIdx.x * blockDim.x + threadIdx.x;
    if (i < Nn) { g_deg[i] = 0; g_cur[i] = 0; }
    if (i < 4 * HIDF) g_sum[i] = 0.f;
    if (i == 0) g_off[Nn] = Ee;
}

__global__ void k_deg(const int* __restrict__ dst) {
    int e = blockIdx.x * blockDim.x + threadIdx.x;
    if (e < Ee) atomicAdd(&g_deg[dst[e]], 1);
}

__global__ void k_dinv() {
    int i = blockIdx.x * blockDim.x + threadIdx.x;
    if (i < Nn) g_dinv[i] = rsqrtf(fmaxf((float)g_deg[i], 1.f));
}

// ------------- multi-block exclusive scan of g_deg -> g_off ------------------
__global__ void k_blocksum() {
    int i = blockIdx.x * 256 + threadIdx.x;
    int v = (i < Nn) ? g_deg[i] : 0;
#pragma unroll
    for (int o = 16; o; o >>= 1) v += __shfl_down_sync(~0u, v, o);
    __shared__ int ws[8];
    if ((threadIdx.x & 31) == 0) ws[threadIdx.x >> 5] = v;
    __syncthreads();
    if (threadIdx.x < 8) {
        int t = ws[threadIdx.x];
#pragma unroll
        for (int o = 4; o; o >>= 1) t += __shfl_down_sync(0xff, t, o);
        if (threadIdx.x == 0) g_bsum[blockIdx.x] = t;
    }
}

__global__ void k_scanb(int nb) {   // single block; exclusive scan of block sums
    int t = threadIdx.x;
    int lane = t & 31, wid = t >> 5;
    int v = (t < nb) ? g_bsum[t] : 0;
    int s = v;
#pragma unroll
    for (int o = 1; o < 32; o <<= 1) {
        int u = __shfl_up_sync(~0u, s, o);
        if (lane >= o) s += u;
    }
    __shared__ int ws[8];
    if (lane == 31) ws[wid] = s;
    __syncthreads();
    if (t < 8) {
        int u = ws[t];
#pragma unroll
        for (int o = 1; o < 8; o <<= 1) {
            int q = __shfl_up_sync(0xff, u, o);
            if (t >= o) u += q;
        }
        ws[t] = u;
    }
    __syncthreads();
    int excl = s - v + (wid ? ws[wid - 1] : 0);
    if (t < nb) g_boff[t] = excl;
}

__global__ void k_scanwrite() {
    int i = blockIdx.x * 256 + threadIdx.x;
    int lane = threadIdx.x & 31, wid = threadIdx.x >> 5;
    int v = (i < Nn) ? g_deg[i] : 0;
    int s = v;
#pragma unroll
    for (int o = 1; o < 32; o <<= 1) {
        int u = __shfl_up_sync(~0u, s, o);
        if (lane >= o) s += u;
    }
    __shared__ int ws[8];
    if (lane == 31) ws[wid] = s;
    __syncthreads();
    if (threadIdx.x < 8) {
        int u = ws[threadIdx.x];
#pragma unroll
        for (int o = 1; o < 8; o <<= 1) {
            int q = __shfl_up_sync(0xff, u, o);
            if (threadIdx.x >= o) u += q;
        }
        ws[threadIdx.x] = u;
    }
    __syncthreads();
    int excl = s - v + (wid ? ws[wid - 1] : 0);
    if (i < Nn) g_off[i] = g_boff[blockIdx.x] + excl;
}

__global__ void k_scatter(const int* __restrict__ src, const int* __restrict__ dst) {
    int e = blockIdx.x * blockDim.x + threadIdx.x;
    if (e < Ee) {
        int s = src[e], d = dst[e];
        int p = atomicAdd(&g_cur[d], 1);
        int idx = g_off[d] + p;
        float w = g_dinv[s] * g_dinv[d];
        g_sw[idx] = make_int2(s, __float_as_int(w));
    }
}

// c_L[j] = gamma_L[j];  c_H[j] = (-1)^j * sum_{k>=j} gamma_H[k] * C(k,j)
__global__ void k_coeff(const float* __restrict__ gL, const float* __restrict__ gH) {
    if (threadIdx.x == 0 && blockIdx.x == 0) {
        double C[KK + 1][KK + 1];
        for (int k = 0; k <= KK; k++)
            for (int j = 0; j <= KK; j++) C[k][j] = 0.0;
        for (int k = 0; k <= KK; k++) {
            C[k][0] = 1.0; C[k][k] = 1.0;
            for (int j = 1; j < k; j++) C[k][j] = C[k - 1][j - 1] + C[k - 1][j];
        }
        for (int j = 0; j <= KK; j++) {
            double s = 0.0;
            for (int k = j; k <= KK; k++) s += (double)gH[k] * C[k][j];
            g_cH[j] = (j & 1) ? (float)(-s) : (float)s;
            g_cL[j] = gL[j];
        }
    }
}

// --------------------- GEMM1 via mma.sync bf16 (3-term split) ---------------
// C[Nn,128] = x[Nn,500] @ W[500,128] + bias.
// x = xh + xl, W = Wh + Wl (bf16 hi/lo), acc += xh*Wh + xh*Wl + xl*Wh (fp32).
// Block tile 64(M) x 128(N), 8 warps in 2x4 grid, warp tile 32x32,
// K chunks of 32 (16 chunks; tail zero-padded).
#define ASTR 34   // smem row stride in bf16 elements (68B, 4B-aligned)

__global__ __launch_bounds__(256)
void k_gemm1_mma(const float* __restrict__ A, const float* __restrict__ B,
                 const float* __restrict__ bias, float* __restrict__ C, int M) {
    __shared__ __nv_bfloat16 Ash[64][ASTR], Asl[64][ASTR];
    __shared__ __nv_bfloat16 Bsh[128][ASTR], Bsl[128][ASTR];
    int tid = threadIdx.x;
    int w = tid >> 5, lane = tid & 31;
    int g = lane >> 2, tig = lane & 3;
    int wm = w & 1, wn = w >> 1;          // warp grid 2(M) x 4(N)
    int row0 = blockIdx.x * 64;

    float acc[2][4][4];
#pragma unroll
    for (int mt = 0; mt < 2; mt++)
#pragma unroll
        for (int nf = 0; nf < 4; nf++)
#pragma unroll
            for (int i = 0; i < 4; i++) acc[mt][nf][i] = 0.f;

    for (int ch = 0; ch < 16; ch++) {
        int k0 = ch * 32;
        // ---- load A chunk: 64 rows x 32 cols fp32 -> bf16 hi/lo ----
        {
            int r = tid >> 2, c0 = (tid & 3) * 8;
            int gr = row0 + r;
#pragma unroll
            for (int i = 0; i < 8; i++) {
                int gc = k0 + c0 + i;
                float v = (gr < M && gc < INF_) ? A[(size_t)gr * INF_ + gc] : 0.f;
                __nv_bfloat16 h = __float2bfloat16(v);
                __nv_bfloat16 l = __float2bfloat16(v - __bfloat162float(h));
                Ash[r][c0 + i] = h;
                Asl[r][c0 + i] = l;
            }
        }
        // ---- load B chunk transposed: Bs[n][kk] = W[k0+kk][n] ----
        {
            int kk = tid >> 3, n0 = (tid & 7) * 16;
            int gk = k0 + kk;
#pragma unroll
            for (int i = 0; i < 16; i++) {
                float v = (gk < INF_) ? B[(size_t)gk * HIDF + n0 + i] : 0.f;
                __nv_bfloat16 h = __float2bfloat16(v);
                __nv_bfloat16 l = __float2bfloat16(v - __bfloat162float(h));
                Bsh[n0 + i][kk] = h;
                Bsl[n0 + i][kk] = l;
            }
        }
        __syncthreads();

#pragma unroll
        for (int ks = 0; ks < 2; ks++) {
            int kb = ks * 16;
            uint32_t ah[2][4], al[2][4];
#pragma unroll
            for (int mt = 0; mt < 2; mt++) {
                int r = wm * 32 + mt * 16 + g;
                int c = kb + tig * 2;
                ah[mt][0] = *(const uint32_t*)&Ash[r][c];
                ah[mt][1] = *(const uint32_t*)&Ash[r + 8][c];
                ah[mt][2] = *(const uint32_t*)&Ash[r][c + 8];
                ah[mt][3] = *(const uint32_t*)&Ash[r + 8][c + 8];
                al[mt][0] = *(const uint32_t*)&Asl[r][c];
                al[mt][1] = *(const uint32_t*)&Asl[r + 8][c];
                al[mt][2] = *(const uint32_t*)&Asl[r][c + 8];
                al[mt][3] = *(const uint32_t*)&Asl[r + 8][c + 8];
            }
#pragma unroll
            for (int nf = 0; nf < 4; nf++) {
                int n = wn * 32 + nf * 8 + g;
                uint32_t bh0 = *(const uint32_t*)&Bsh[n][kb + tig * 2];
                uint32_t bh1 = *(const uint32_t*)&Bsh[n][kb + tig * 2 + 8];
                uint32_t bl0 = *(const uint32_t*)&Bsl[n][kb + tig * 2];
                uint32_t bl1 = *(const uint32_t*)&Bsl[n][kb + tig * 2 + 8];
#pragma unroll
                for (int mt = 0; mt < 2; mt++) {
                    MMA_BF16(acc[mt][nf], ah[mt], bh0, bh1);
                    MMA_BF16(acc[mt][nf], ah[mt], bl0, bl1);
                    MMA_BF16(acc[mt][nf], al[mt], bh0, bh1);
                }
            }
        }
        __syncthreads();
    }

    // ---- epilogue: c0,c1 -> (g, 2t, 2t+1); c2,c3 -> (g+8, ...) ----
#pragma unroll
    for (int mt = 0; mt < 2; mt++) {
#pragma unroll
        for (int nf = 0; nf < 4; nf++) {
            int col = wn * 32 + nf * 8 + tig * 2;
            int gr0 = row0 + wm * 32 + mt * 16 + g;
            int gr1 = gr0 + 8;
            if (gr0 < M) {
                C[(size_t)gr0 * HIDF + col]     = acc[mt][nf][0] + bias[col];
                C[(size_t)gr0 * HIDF + col + 1] = acc[mt][nf][1] + bias[col + 1];
            }
            if (gr1 < M) {
                C[(size_t)gr1 * HIDF + col]     = acc[mt][nf][2] + bias[col];
                C[(size_t)gr1 * HIDF + col + 1] = acc[mt][nf][3] + bias[col + 1];
            }
        }
    }
}

// ------------- Epilogue GEMM via mma.sync bf16 (3-term split) ---------------
// out = relu((A*alpha + beta) @ W_up + b_up), K = 128 (4 chunks of 32).
// Both branches in one launch (blockIdx.y). BN-affine applied at A-tile load
// (pre-split, so the split operates on O(1) normalized values).
__global__ __launch_bounds__(256)
void k_gemm_ep_mma(const float* __restrict__ AL, const float* __restrict__ AH,
                   const float* __restrict__ B, const float* __restrict__ bias,
                   float* __restrict__ out, int M) {
    __shared__ __nv_bfloat16 Ash[64][ASTR], Asl[64][ASTR];
    __shared__ __nv_bfloat16 Bsh[128][ASTR], Bsl[128][ASTR];
    int br = blockIdx.y;
    const float* __restrict__ A = br ? AH : AL;
    const float* __restrict__ alpha = g_alpha + br * HIDF;
    const float* __restrict__ beta  = g_beta  + br * HIDF;
    float* __restrict__ C = out + (size_t)br * Nn * HIDF;

    int tid = threadIdx.x;
    int w = tid >> 5, lane = tid & 31;
    int g = lane >> 2, tig = lane & 3;
    int wm = w & 1, wn = w >> 1;
    int row0 = blockIdx.x * 64;

    float acc[2][4][4];
#pragma unroll
    for (int mt = 0; mt < 2; mt++)
#pragma unroll
        for (int nf = 0; nf < 4; nf++)
#pragma unroll
            for (int i = 0; i < 4; i++) acc[mt][nf][i] = 0.f;

#pragma unroll
    for (int ch = 0; ch < 4; ch++) {
        int k0 = ch * 32;
        // ---- A chunk with BN affine: 64 x 32 ----
        {
            int r = tid >> 2, c0 = (tid & 3) * 8;
            int gr = row0 + r;
#pragma unroll
            for (int i = 0; i < 8; i++) {
                int gc = k0 + c0 + i;
                float v = 0.f;
                if (gr < M) v = fmaf(A[(size_t)gr * HIDF + gc], alpha[gc], beta[gc]);
                __nv_bfloat16 h = __float2bfloat16(v);
                __nv_bfloat16 l = __float2bfloat16(v - __bfloat162float(h));
                Ash[r][c0 + i] = h;
                Asl[r][c0 + i] = l;
            }
        }
        // ---- B chunk transposed: Bs[n][kk] = W_up[k0+kk][n] ----
        {
            int kk = tid >> 3, n0 = (tid & 7) * 16;
            int gk = k0 + kk;
#pragma unroll
            for (int i = 0; i < 16; i++) {
                float v = B[(size_t)gk * HIDF + n0 + i];
                __nv_bfloat16 h = __float2bfloat16(v);
                __nv_bfloat16 l = __float2bfloat16(v - __bfloat162float(h));
                Bsh[n0 + i][kk] = h;
                Bsl[n0 + i][kk] = l;
            }
        }
        __syncthreads();

#pragma unroll
        for (int ks = 0; ks < 2; ks++) {
            int kb = ks * 16;
            uint32_t ah[2][4], al[2][4];
#pragma unroll
            for (int mt = 0; mt < 2; mt++) {
                int r = wm * 32 + mt * 16 + g;
                int c = kb + tig * 2;
                ah[mt][0] = *(const uint32_t*)&Ash[r][c];
                ah[mt][1] = *(const uint32_t*)&Ash[r + 8][c];
                ah[mt][2] = *(const uint32_t*)&Ash[r][c + 8];
                ah[mt][3] = *(const uint32_t*)&Ash[r + 8][c + 8];
                al[mt][0] = *(const uint32_t*)&Asl[r][c];
                al[mt][1] = *(const uint32_t*)&Asl[r + 8][c];
                al[mt][2] = *(const uint32_t*)&Asl[r][c + 8];
                al[mt][3] = *(const uint32_t*)&Asl[r + 8][c + 8];
            }
#pragma unroll
            for (int nf = 0; nf < 4; nf++) {
                int n = wn * 32 + nf * 8 + g;
                uint32_t bh0 = *(const uint32_t*)&Bsh[n][kb + tig * 2];
                uint32_t bh1 = *(const uint32_t*)&Bsh[n][kb + tig * 2 + 8];
                uint32_t bl0 = *(const uint32_t*)&Bsl[n][kb + tig * 2];
                uint32_t bl1 = *(const uint32_t*)&Bsl[n][kb + tig * 2 + 8];
#pragma unroll
                for (int mt = 0; mt < 2; mt++) {
                    MMA_BF16(acc[mt][nf], ah[mt], bh0, bh1);
                    MMA_BF16(acc[mt][nf], ah[mt], bl0, bl1);
                    MMA_BF16(acc[mt][nf], al[mt], bh0, bh1);
                }
            }
        }
        __syncthreads();
    }

#pragma unroll
    for (int mt = 0; mt < 2; mt++) {
#pragma unroll
        for (int nf = 0; nf < 4; nf++) {
            int col = wn * 32 + nf * 8 + tig * 2;
            int gr0 = row0 + wm * 32 + mt * 16 + g;
            int gr1 = gr0 + 8;
            if (gr0 < M) {
                C[(size_t)gr0 * HIDF + col]     = fmaxf(acc[mt][nf][0] + bias[col], 0.f);
                C[(size_t)gr0 * HIDF + col + 1] = fmaxf(acc[mt][nf][1] + bias[col + 1], 0.f);
            }
            if (gr1 < M) {
                C[(size_t)gr1 * HIDF + col]     = fmaxf(acc[mt][nf][2] + bias[col], 0.f);
                C[(size_t)gr1 * HIDF + col + 1] = fmaxf(acc[mt][nf][3] + bias[col + 1], 0.f);
            }
        }
    }
}

// --------------------------- sparse propagation (866-proven) -----------------
__global__ __launch_bounds__(256)
void k_prop(int j) {
    int node = blockIdx.x * 8 + (threadIdx.x >> 5);
    if (node >= Nn) return;
    int lane = threadIdx.x & 31;
    const float4* __restrict__ tin = (const float4*)g_P[j - 1];
    float4* __restrict__ tout = (float4*)g_P[j];
    int beg = g_off[node], end = g_off[node + 1];
    float sx = 0.f, sy = 0.f, sz = 0.f, sw = 0.f;
    int e = beg;
    for (; e + 4 <= end; e += 4) {
        int2 a0 = g_sw[e],     a1 = g_sw[e + 1];
        int2 a2 = g_sw[e + 2], a3 = g_sw[e + 3];
        float4 v0 = __ldg(&tin[a0.x * 32 + lane]);
        float4 v1 = __ldg(&tin[a1.x * 32 + lane]);
        float4 v2 = __ldg(&tin[a2.x * 32 + lane]);
        float4 v3 = __ldg(&tin[a3.x * 32 + lane]);
        float w0 = __int_as_float(a0.y), w1 = __int_as_float(a1.y);
        float w2 = __int_as_float(a2.y), w3 = __int_as_float(a3.y);
        sx = fmaf(w0, v0.x, sx); sy = fmaf(w0, v0.y, sy);
        sz = fmaf(w0, v0.z, sz); sw = fmaf(w0, v0.w, sw);
        sx = fmaf(w1, v1.x, sx); sy = fmaf(w1, v1.y, sy);
        sz = fmaf(w1, v1.z, sz); sw = fmaf(w1, v1.w, sw);
        sx = fmaf(w2, v2.x, sx); sy = fmaf(w2, v2.y, sy);
        sz = fmaf(w2, v2.z, sz); sw = fmaf(w2, v2.w, sw);
        sx = fmaf(w3, v3.x, sx); sy = fmaf(w3, v3.y, sy);
        sz = fmaf(w3, v3.z, sz); sw = fmaf(w3, v3.w, sw);
    }
    for (; e < end; e++) {
        int2 a0 = g_sw[e];
        float w0 = __int_as_float(a0.y);
        float4 v0 = __ldg(&tin[a0.x * 32 + lane]);
        sx = fmaf(w0, v0.x, sx); sy = fmaf(w0, v0.y, sy);
        sz = fmaf(w0, v0.z, sz); sw = fmaf(w0, v0.w, sw);
    }
    tout[node * 32 + lane] = make_float4(sx, sy, sz, sw);
}

// --------------------------- combine + BN partials ---------------------------
__global__ __launch_bounds__(256)
void k_combine() {
    int tid = threadIdx.x;
    int fq = tid & 31;
    int wid = tid >> 5;
    float cl[KK + 1], ch[KK + 1];
#pragma unroll
    for (int j = 0; j <= KK; j++) { cl[j] = g_cL[j]; ch[j] = g_cH[j]; }

    float4 psL = {0, 0, 0, 0}, pqL = {0, 0, 0, 0};
    float4 psH = {0, 0, 0, 0}, pqH = {0, 0, 0, 0};

    for (int node = blockIdx.x * 8 + wid; node < Nn; node += gridDim.x * 8) {
        int base = node * 32 + fq;
        float4 aL = {0, 0, 0, 0}, aH = {0, 0, 0, 0};
#pragma unroll
        for (int j = 0; j <= KK; j++) {
            float4 p = ((const float4*)g_P[j])[base];
            aL.x = fmaf(cl[j], p.x, aL.x); aL.y = fmaf(cl[j], p.y, aL.y);
            aL.z = fmaf(cl[j], p.z, aL.z); aL.w = fmaf(cl[j], p.w, aL.w);
            aH.x = fmaf(ch[j], p.x, aH.x); aH.y = fmaf(ch[j], p.y, aH.y);
            aH.z = fmaf(ch[j], p.z, aH.z); aH.w = fmaf(ch[j], p.w, aH.w);
        }
        ((float4*)g_accL)[base] = aL;
        ((float4*)g_accH)[base] = aH;
        psL.x += aL.x; psL.y += aL.y; psL.z += aL.z; psL.w += aL.w;
        pqL.x = fmaf(aL.x, aL.x, pqL.x); pqL.y = fmaf(aL.y, aL.y, pqL.y);
        pqL.z = fmaf(aL.z, aL.z, pqL.z); pqL.w = fmaf(aL.w, aL.w, pqL.w);
        psH.x += aH.x; psH.y += aH.y; psH.z += aH.z; psH.w += aH.w;
        pqH.x = fmaf(aH.x, aH.x, pqH.x); pqH.y = fmaf(aH.y, aH.y, pqH.y);
        pqH.z = fmaf(aH.z, aH.z, pqH.z); pqH.w = fmaf(aH.w, aH.w, pqH.w);
    }

    __shared__ float4 sh[4][256];
    sh[0][tid] = psL; sh[1][tid] = pqL; sh[2][tid] = psH; sh[3][tid] = pqH;
    __syncthreads();
    if (tid < 32) {
        float4 a0 = sh[0][tid], a1 = sh[1][tid], a2 = sh[2][tid], a3 = sh[3][tid];
#pragma unroll
        for (int w = 1; w < 8; w++) {
            float4 t;
            t = sh[0][tid + 32 * w]; a0.x += t.x; a0.y += t.y; a0.z += t.z; a0.w += t.w;
            t = sh[1][tid + 32 * w]; a1.x += t.x; a1.y += t.y; a1.z += t.z; a1.w += t.w;
            t = sh[2][tid + 32 * w]; a2.x += t.x; a2.y += t.y; a2.z += t.z; a2.w += t.w;
            t = sh[3][tid + 32 * w]; a3.x += t.x; a3.y += t.y; a3.z += t.z; a3.w += t.w;
        }
        int f = tid * 4;
        atomicAdd(&g_sum[0 * HIDF + f + 0], a0.x); atomicAdd(&g_sum[0 * HIDF + f + 1], a0.y);
        atomicAdd(&g_sum[0 * HIDF + f + 2], a0.z); atomicAdd(&g_sum[0 * HIDF + f + 3], a0.w);
        atomicAdd(&g_sum[1 * HIDF + f + 0], a1.x); atomicAdd(&g_sum[1 * HIDF + f + 1], a1.y);
        atomicAdd(&g_sum[1 * HIDF + f + 2], a1.z); atomicAdd(&g_sum[1 * HIDF + f + 3], a1.w);
        atomicAdd(&g_sum[2 * HIDF + f + 0], a2.x); atomicAdd(&g_sum[2 * HIDF + f + 1], a2.y);
        atomicAdd(&g_sum[2 * HIDF + f + 2], a2.z); atomicAdd(&g_sum[2 * HIDF + f + 3], a2.w);
        atomicAdd(&g_sum[3 * HIDF + f + 0], a3.x); atomicAdd(&g_sum[3 * HIDF + f + 1], a3.y);
        atomicAdd(&g_sum[3 * HIDF + f + 2], a3.z); atomicAdd(&g_sum[3 * HIDF + f + 3], a3.w);
    }
}

__global__ void k_bnfinal(const float* __restrict__ bn_scale,
                          const float* __restrict__ bn_shift) {
    int f = threadIdx.x;
    if (f < HIDF) {
        const float invN = 1.f / (float)Nn;
        float mu = g_sum[f] * invN;
        float var = g_sum[HIDF + f] * invN - mu * mu;
        float a = rsqrtf(var + 1e-5f) * bn_scale[f];
        g_alpha[f] = a;
        g_beta[f] = bn_shift[f] - mu * a;
        mu = g_sum[2 * HIDF + f] * invN;
        var = g_sum[3 * HIDF + f] * invN - mu * mu;
        a = rsqrtf(var + 1e-5f) * bn_scale[f];
        g_alpha[HIDF + f] = a;
        g_beta[HIDF + f] = bn_shift[f] - mu * a;
    }
}

// ------------------------------- launcher ------------------------------------
extern "C" void kernel_launch(void* const* d_in, const int* in_sizes, int n_in,
                              void* d_out, int out_size) {
    const float* x    = (const float*)d_in[0];
    const int*   ei   = (const int*)d_in[1];
    const float* W_in = (const float*)d_in[2];
    const float* b_in = (const float*)d_in[3];
    const float* gL   = (const float*)d_in[4];
    const float* gH   = (const float*)d_in[5];
    const float* bns  = (const float*)d_in[6];
    const float* bnb  = (const float*)d_in[7];
    const float* W_up = (const float*)d_in[8];
    const float* b_up = (const float*)d_in[9];
    float* out = (float*)d_out;

    const int* src = ei;
    const int* dst = ei + Ee;

    void *pP, *pAL, *pAH;
    cudaGetSymbolAddress(&pP,  g_P);
    cudaGetSymbolAddress(&pAL, g_accL);
    cudaGetSymbolAddress(&pAH, g_accH);
    float* P0   = (float*)pP;                  // g_P[0]
    float* accL = (float*)pAL;
    float* accH = (float*)pAH;

    const int nblkN = (Nn + 255) / 256;   // 196
    const int nblkE = (Ee + 255) / 256;   // 3125
    const int gemmB = (Nn + 63) / 64;     // 782

    k_init<<<nblkN, 256>>>();
    k_deg<<<nblkE, 256>>>(dst);
    k_dinv<<<nblkN, 256>>>();
    k_blocksum<<<nblkN, 256>>>();
    k_scanb<<<1, 256>>>(nblkN);
    k_scanwrite<<<nblkN, 256>>>();
    k_scatter<<<nblkE, 256>>>(src, dst);
    k_coeff<<<1, 32>>>(gL, gH);

    // p_0 = h = x @ W_in + b_in   (tensor-core bf16 3-term split via mma.sync)
    k_gemm1_mma<<<gemmB, 256>>>(x, W_in, b_in, P0, Nn);

    // Krylov chain p_j = A p_{j-1}
    for (int j = 1; j <= KK; j++)
        k_prop<<<(Nn + 7) / 8, 256>>>(j);

    // acc_L / acc_H + BN statistics
    k_combine<<<296, 256>>>();
    k_bnfinal<<<1, 128>>>(bns, bnb);

    // Z = relu(BN(acc) @ W_up + b_up), both branches, tensor-core path
    dim3 epg(gemmB, 2);
    k_gemm_ep_mma<<<epg, 256>>>(accL, accH, W_up, b_up, out, Nn);
}